// round 14
// baseline (speedup 1.0000x reference)
#include <cuda_runtime.h>
#include <cuda_fp16.h>
#include <math.h>
#include <stdint.h>

// Problem constants
#define Bz 8
#define Nn 1024
#define Mm 32
#define BN (Bz*Nn)            // 8192
#define KFREQ (-0.6140226914650789f)   // -log(10000)/15

#define EDGE_GRID 148
#define WARPS_PER_CTA 14
#define EDGE_THREADS (WARPS_PER_CTA * 32)             // 448
#define NODES_PER_ITER (EDGE_GRID * WARPS_PER_CTA)    // 2072
#define NITER 4                                        // ceil(8192/2072)

// Edge weight image (bytes): B1 | B2   (plain fp16)
#define OFF_B1 0
#define OFF_B2 18432
#define WIMG_BYTES 53248

// Proj weight image: [W1a^T | W1b^T | Wh1a^T] -> 3 x [128 n][128 k] fp16, stride 272B
#define PIMG_HALF  34816
#define PIMG_BYTES (3 * PIMG_HALF)

// Node weight image: W2h^T | Wh2^T  each [128 n][128 k] fp16, stride 272B
#define OFF_W2H 0
#define OFF_WH2 34816
#define NIMG_BYTES 69632

// ---------------------------------------------------------------------------
// Scratch
// ---------------------------------------------------------------------------
__device__ float    g_p1[BN*128];    // emb @ W1[0:128]
__device__ uint32_t g_p2h[BN*64];    // emb @ W1[128:256], packed half2
__device__ float    g_p3[BN*128];    // emb @ Wh1a + bh1
__device__ float    g_hsum[BN*128];  // sum_j relu-h
__device__ float    g_b2x[128];      // b2 @ Wx1 + bx1
__device__ float    g_bvec[128];     // b2 @ Wh1[128:256]
__device__ uint4 g_Bimg[WIMG_BYTES/16];
__device__ uint4 g_Pimg[PIMG_BYTES/16];
__device__ uint4 g_Nimg[NIMG_BYTES/16];

// ---------------------------------------------------------------------------
// helpers
// ---------------------------------------------------------------------------
__device__ __forceinline__ uint32_t s2u(const void* p) {
    uint32_t a;
    asm("{ .reg .u64 t; cvta.to.shared.u64 t, %1; cvt.u32.u64 %0, t; }"
        : "=r"(a) : "l"(p));
    return a;
}
__device__ __forceinline__ void ldmx4(uint32_t& r0, uint32_t& r1,
                                      uint32_t& r2, uint32_t& r3, uint32_t addr) {
    asm volatile("ldmatrix.sync.aligned.m8n8.x4.shared.b16 {%0,%1,%2,%3}, [%4];"
                 : "=r"(r0), "=r"(r1), "=r"(r2), "=r"(r3) : "r"(addr));
}
__device__ __forceinline__ void mma16816(float* c, const uint32_t* a,
                                         uint32_t b0, uint32_t b1) {
    asm volatile(
        "mma.sync.aligned.m16n8k16.row.col.f32.f16.f16.f32 "
        "{%0,%1,%2,%3}, {%4,%5,%6,%7}, {%8,%9}, {%0,%1,%2,%3};"
        : "+f"(c[0]), "+f"(c[1]), "+f"(c[2]), "+f"(c[3])
        : "r"(a[0]), "r"(a[1]), "r"(a[2]), "r"(a[3]), "r"(b0), "r"(b1));
}
// pack: lower half = f0, upper = f1
__device__ __forceinline__ uint32_t packhf(float f0, float f1) {
    uint32_t r;
    asm("cvt.rn.f16x2.f32 %0, %1, %2;" : "=r"(r) : "f"(f1), "f"(f0));
    return r;
}
__device__ __forceinline__ float2 unpackhf(uint32_t v) {
    __half2 h = *(__half2*)&v;
    return __half22float2(h);
}

// ---------------------------------------------------------------------------
// K-1: fold + all weight-image prep.
// ---------------------------------------------------------------------------
__global__ __launch_bounds__(128) void k_fold(
    const float* __restrict__ w2,  const float* __restrict__ b2,
    const float* __restrict__ wx1, const float* __restrict__ bx1,
    const float* __restrict__ wh1, const float* __restrict__ w1,
    const float* __restrict__ wh2)
{
    __shared__ float w2sh[16][128];
    unsigned char* img  = (unsigned char*)g_Bimg;
    unsigned char* img2 = (unsigned char*)g_Pimg;
    unsigned char* img3 = (unsigned char*)g_Nimg;
    const int c = threadIdx.x;
    const int d0 = blockIdx.x * 16;

    #pragma unroll
    for (int i = 0; i < 16; i++)
        w2sh[i][c] = w2[(d0 + i) * 128 + c];
    __syncthreads();

    float a1[16], a2[16];
    #pragma unroll
    for (int i = 0; i < 16; i++) { a1[i] = 0.f; a2[i] = 0.f; }

    #pragma unroll 2
    for (int k = 0; k < 128; k++) {
        float wA = wx1[k * 128 + c];
        float wB = wh1[(128 + k) * 128 + c];
        #pragma unroll
        for (int i = 0; i < 16; i++) {
            float v = w2sh[i][k];
            a1[i] = fmaf(v, wA, a1[i]);
            a2[i] = fmaf(v, wB, a2[i]);
        }
    }
    #pragma unroll
    for (int i = 0; i < 16; i++) {
        *(__half*)(img + OFF_B2 + (uint32_t)c * 272 + (uint32_t)(d0 + i) * 2)
            = __float2half_rn(a1[i]);
        *(__half*)(img3 + OFF_W2H + (uint32_t)c * 272 + (uint32_t)(d0 + i) * 2)
            = __float2half_rn(a2[i]);
    }

    // B1 image
    #pragma unroll
    for (int j = 0; j < 8; j++) {
        int e = blockIdx.x * 1024 + j * 128 + c;
        int n = e & 127, k = e >> 7;
        *(__half*)(img + OFF_B1 + (uint32_t)n * 144 + (uint32_t)k * 2)
            = __float2half_rn(w1[(256 + k) * 128 + n]);
    }

    // Proj image: n<256: W1ab^T;  n>=256: Wh1a^T   (n-major slices of 128)
    #pragma unroll
    for (int j = 0; j < 48; j++) {
        int e = blockIdx.x * 6144 + j * 128 + c;
        int k = e / 384;
        int n = e - k * 384;
        float v = (n < 256) ? w1[(k + ((n >> 7) << 7)) * 128 + (n & 127)]
                            : wh1[k * 128 + (n - 256)];
        *(__half*)(img2 + (uint32_t)n * 272 + (uint32_t)k * 2)
            = __float2half_rn(v);
    }

    // Wh2 image
    #pragma unroll
    for (int j = 0; j < 16; j++) {
        int e = blockIdx.x * 2048 + j * 128 + c;
        int n = e & 127, k = e >> 7;
        *(__half*)(img3 + OFF_WH2 + (uint32_t)n * 272 + (uint32_t)k * 2)
            = __float2half_rn(wh2[k * 128 + n]);
    }

    if (blockIdx.x == 0) {
        float s1 = bx1[c], s2 = 0.f;
        for (int k = 0; k < 128; k++) {
            float bk = b2[k];
            s1 = fmaf(bk, wx1[k * 128 + c], s1);
            s2 = fmaf(bk, wh1[(128 + k) * 128 + c], s2);
        }
        g_b2x[c]  = s1;
        g_bvec[c] = s2;
    }
}

// ---------------------------------------------------------------------------
// K0: HMMA projection, all 3 slices in one pass.  grid 128, block 128.
// Warp = 16 rows; A fragments computed once; 102KB image in smem.
// ---------------------------------------------------------------------------
__global__ __launch_bounds__(128) void k_proj(
    const float* __restrict__ emb, const float* __restrict__ bh1g)
{
    extern __shared__ unsigned char psm[];
    const uint32_t sbp = s2u(psm);

    const int tid  = threadIdx.x;
    const int w    = tid >> 5;
    const int lane = tid & 31;
    const int td4  = lane >> 2;
    const int tm4  = lane & 3;

    { // full proj image gmem -> smem (102KB)
        uint4* dst = (uint4*)psm;
        for (int i = tid; i < PIMG_BYTES / 16; i += 128) dst[i] = g_Pimg[i];
    }
    __syncthreads();

    const int node0 = blockIdx.x * 64 + w * 16;

    // A fragments once: K=128 -> 8 ktiles x 4 regs (single m16 tile)
    uint32_t af[8][4];
    #pragma unroll
    for (int kt = 0; kt < 8; kt++) {
        #pragma unroll
        for (int i = 0; i < 2; i++) {
            int row = node0 + td4 + 8 * i;
            const float* ep = emb + (size_t)row * 128 + kt * 16 + 2 * tm4;
            float2 va = *(const float2*)ep;
            float2 vb = *(const float2*)(ep + 8);
            af[kt][i]     = packhf(va.x, va.y);
            af[kt][2 + i] = packhf(vb.x, vb.y);
        }
    }

    const int qsel  = lane >> 3;
    const int ntoff = qsel >> 1;
    const int khalf = qsel & 1;

    #pragma unroll
    for (int slice = 0; slice < 3; slice++) {
        const uint32_t base = sbp + (uint32_t)slice * PIMG_HALF;
        #pragma unroll
        for (int chunk = 0; chunk < 2; chunk++) {
            float cc[8][4];
            #pragma unroll
            for (int nt = 0; nt < 8; nt++)
            #pragma unroll
            for (int q = 0; q < 4; q++) cc[nt][q] = 0.f;

            #pragma unroll
            for (int kt = 0; kt < 8; kt++) {
                #pragma unroll
                for (int nt2 = 0; nt2 < 4; nt2++) {
                    const int ntq = chunk * 8 + 2 * nt2 + ntoff;
                    uint32_t off = (uint32_t)((ntq * 8 + (lane & 7)) * 136
                                              + kt * 16 + khalf * 8) * 2;
                    uint32_t p0, p1, p2, p3;
                    ldmx4(p0, p1, p2, p3, base + off);
                    mma16816(cc[2 * nt2 + 0], af[kt], p0, p1);
                    mma16816(cc[2 * nt2 + 1], af[kt], p2, p3);
                }
            }
            #pragma unroll
            for (int ntl = 0; ntl < 8; ntl++) {
                const int col = (chunk * 8 + ntl) * 8 + 2 * tm4;
                float2 bb = make_float2(0.f, 0.f);
                if (slice == 2) bb = *(const float2*)(bh1g + col);
                #pragma unroll
                for (int mh = 0; mh < 2; mh++) {
                    int row = node0 + td4 + 8 * mh;
                    float v0 = cc[ntl][2 * mh + 0] + bb.x;
                    float v1 = cc[ntl][2 * mh + 1] + bb.y;
                    if (slice == 0)
                        *(float2*)(g_p1 + (size_t)row * 128 + col) = make_float2(v0, v1);
                    else if (slice == 1)
                        g_p2h[(size_t)row * 64 + (col >> 1)] = packhf(v0, v1);
                    else
                        *(float2*)(g_p3 + (size_t)row * 128 + col) = make_float2(v0, v1);
                }
            }
        }
    }
}

// ---------------------------------------------------------------------------
// K1: HMMA edge kernel.  448 threads (14 warps), warp = node, 4 iterations.
// ---------------------------------------------------------------------------
__global__ __launch_bounds__(EDGE_THREADS, 1) void k_edge(
    const float* __restrict__ coords,
    const float* __restrict__ edges,
    const float* __restrict__ b1g,
    const float* __restrict__ wx2, const float* __restrict__ bx2,
    const int* __restrict__ ids,
    float* __restrict__ out_coords)
{
    extern __shared__ unsigned char wsm[];
    const uint32_t sb  = s2u(wsm);
    const uint32_t b1A = sb + OFF_B1;
    const uint32_t b2A = sb + OFF_B2;

    __shared__ float dist_sh[EDGE_THREADS];
    __shared__ float unit_sh[EDGE_THREADS][3];
    __shared__ int   jid_sh[EDGE_THREADS];
    __shared__ float px_sh[EDGE_THREADS];
    __shared__ float b1_sh[128], b2x_sh[128], wx2_sh[128], fr_sh[16];

    const int tid  = threadIdx.x;
    const int w    = tid >> 5;
    const int lane = tid & 31;
    const int td4  = lane >> 2;
    const int tm4  = lane & 3;

    {
        uint4* dst = (uint4*)wsm;
        for (int i = tid; i < WIMG_BYTES / 16; i += EDGE_THREADS) dst[i] = g_Bimg[i];
    }
    if (tid < 128) {
        b1_sh[tid]  = b1g[tid];
        b2x_sh[tid] = g_b2x[tid];
        wx2_sh[tid] = wx2[tid];
    }
    if (tid < 16) fr_sh[tid] = expf((float)tid * KFREQ);
    __syncthreads();

    const float fr0 = fr_sh[2 * tm4],     fr1 = fr_sh[2 * tm4 + 1];
    const float fr2 = fr_sh[2 * tm4 + 8], fr3 = fr_sh[2 * tm4 + 9];
    const float bx2v = bx2[0];

    const int qsel  = lane >> 3;
    const int ntoff = qsel >> 1;
    const int khalf = qsel & 1;

    for (int it = 0; it < NITER; it++) {
        const int nodebase = it * NODES_PER_ITER + blockIdx.x * WARPS_PER_CTA;

        {
            int nd = nodebase + (tid >> 5);
            if (nd < BN) {
                int m = tid & 31;
                int jabs = ((nd >> 10) << 10) + ids[nd * 32 + m];
                jid_sh[tid] = jabs;
                float dx = coords[nd * 3 + 0] - coords[jabs * 3 + 0];
                float dy = coords[nd * 3 + 1] - coords[jabs * 3 + 1];
                float dz = coords[nd * 3 + 2] - coords[jabs * 3 + 2];
                float d = sqrtf(dx * dx + dy * dy + dz * dz);
                dist_sh[tid] = d;
                float inv = (d > 0.f) ? (1.f / d) : 0.f;
                unit_sh[tid][0] = dx * inv;
                unit_sh[tid][1] = dy * inv;
                unit_sh[tid][2] = dz * inv;
            }
        }
        __syncthreads();

        const int node = nodebase + w;
        if (node < BN) {
            float dloc[4];
            #pragma unroll
            for (int i = 0; i < 4; i++) dloc[i] = dist_sh[w * 32 + td4 + 8 * i];

            uint32_t ahi[4][2][4];
            #pragma unroll
            for (int kt = 0; kt < 4; kt++) {
                #pragma unroll
                for (int i = 0; i < 4; i++) {
                    float v0, v1, v2, v3;
                    if (kt == 0) {
                        v0 = __sinf(dloc[i] * fr0); v1 = __sinf(dloc[i] * fr1);
                        v2 = __sinf(dloc[i] * fr2); v3 = __sinf(dloc[i] * fr3);
                    } else if (kt == 1) {
                        v0 = __cosf(dloc[i] * fr0); v1 = __cosf(dloc[i] * fr1);
                        v2 = __cosf(dloc[i] * fr2); v3 = __cosf(dloc[i] * fr3);
                    } else {
                        const float* ep = edges
                            + (size_t)(node * 32 + td4 + 8 * i) * 32
                            + (kt - 2) * 16 + 2 * tm4;
                        float2 va = *(const float2*)ep;
                        float2 vb = *(const float2*)(ep + 8);
                        v0 = va.x; v1 = va.y; v2 = vb.x; v3 = vb.y;
                    }
                    int mt = i >> 1, s = i & 1;
                    ahi[kt][mt][s]     = packhf(v0, v1);
                    ahi[kt][mt][2 + s] = packhf(v2, v3);
                }
            }

            uint32_t a2[2][8][4];
            #pragma unroll
            for (int half = 0; half < 2; half++) {
                float c1h[2][8][4];
                #pragma unroll
                for (int mt = 0; mt < 2; mt++)
                #pragma unroll
                for (int nt = 0; nt < 8; nt++)
                #pragma unroll
                for (int q = 0; q < 4; q++) c1h[mt][nt][q] = 0.f;

                #pragma unroll
                for (int kt = 0; kt < 4; kt++) {
                    #pragma unroll
                    for (int nt2 = 0; nt2 < 4; nt2++) {
                        const int ntq = half * 8 + 2 * nt2 + ntoff;
                        uint32_t off = (uint32_t)((ntq * 8 + (lane & 7)) * 72
                                                  + kt * 16 + khalf * 8) * 2;
                        uint32_t p0, p1, p2, p3;
                        ldmx4(p0, p1, p2, p3, b1A + off);
                        #pragma unroll
                        for (int mt = 0; mt < 2; mt++) {
                            mma16816(c1h[mt][2 * nt2 + 0], ahi[kt][mt], p0, p1);
                            mma16816(c1h[mt][2 * nt2 + 1], ahi[kt][mt], p2, p3);
                        }
                    }
                }

                #pragma unroll
                for (int kt2l = 0; kt2l < 4; kt2l++) {
                    #pragma unroll
                    for (int sub = 0; sub < 2; sub++) {
                        const int ntl = 2 * kt2l + sub;
                        const int n0c = (half * 8 + ntl) * 8 + 2 * tm4;
                        float2 pa = *(const float2*)(g_p1 + (size_t)node * 128 + n0c);
                        const float bb0 = b1_sh[n0c], bb1 = b1_sh[n0c + 1];
                        float hs0 = 0.f, hs1 = 0.f;
                        #pragma unroll
                        for (int mt = 0; mt < 2; mt++) {
                            #pragma unroll
                            for (int mh = 0; mh < 2; mh++) {
                                int j = jid_sh[w * 32 + td4 + 8 * (2 * mt + mh)];
                                float2 p2v = unpackhf(g_p2h[(size_t)j * 64 + (n0c >> 1)]);
                                float h0 = fmaxf(c1h[mt][ntl][2 * mh + 0] + pa.x + p2v.x + bb0, 0.f);
                                float h1 = fmaxf(c1h[mt][ntl][2 * mh + 1] + pa.y + p2v.y + bb1, 0.f);
                                hs0 += h0; hs1 += h1;
                                a2[mt][half * 4 + kt2l][mh + 2 * sub] = packhf(h0, h1);
                            }
                        }
                        #pragma unroll
                        for (int o = 4; o < 32; o <<= 1) {
                            hs0 += __shfl_xor_sync(0xffffffffu, hs0, o);
                            hs1 += __shfl_xor_sync(0xffffffffu, hs1, o);
                        }
                        if (td4 == 0) {
                            g_hsum[(size_t)node * 128 + n0c]     = hs0;
                            g_hsum[(size_t)node * 128 + n0c + 1] = hs1;
                        }
                    }
                }
            }

            float px[4] = {0.f, 0.f, 0.f, 0.f};
            #pragma unroll
            for (int half = 0; half < 2; half++) {
                #pragma unroll
                for (int q4 = 0; q4 < 2; q4++) {
                    float c2q[2][4][4];
                    #pragma unroll
                    for (int mt = 0; mt < 2; mt++)
                    #pragma unroll
                    for (int nl = 0; nl < 4; nl++)
                    #pragma unroll
                    for (int q = 0; q < 4; q++) c2q[mt][nl][q] = 0.f;

                    #pragma unroll
                    for (int kt2 = 0; kt2 < 8; kt2++) {
                        #pragma unroll
                        for (int nl2 = 0; nl2 < 2; nl2++) {
                            const int ntq = half * 8 + q4 * 4 + 2 * nl2 + ntoff;
                            uint32_t off = (uint32_t)((ntq * 8 + (lane & 7)) * 136
                                                      + kt2 * 16 + khalf * 8) * 2;
                            uint32_t p0, p1, p2, p3;
                            ldmx4(p0, p1, p2, p3, b2A + off);
                            #pragma unroll
                            for (int mt = 0; mt < 2; mt++) {
                                mma16816(c2q[mt][2 * nl2 + 0], a2[mt][kt2], p0, p1);
                                mma16816(c2q[mt][2 * nl2 + 1], a2[mt][kt2], p2, p3);
                            }
                        }
                    }
                    #pragma unroll
                    for (int nl = 0; nl < 4; nl++) {
                        const int n = half * 64 + q4 * 32 + nl * 8 + 2 * tm4;
                        const float bA = b2x_sh[n], bB = b2x_sh[n + 1];
                        const float wA = wx2_sh[n], wB = wx2_sh[n + 1];
                        #pragma unroll
                        for (int mt = 0; mt < 2; mt++) {
                            px[2 * mt + 0] = fmaf(fmaxf(c2q[mt][nl][0] + bA, 0.f), wA,
                                             fmaf(fmaxf(c2q[mt][nl][1] + bB, 0.f), wB,
                                                  px[2 * mt + 0]));
                            px[2 * mt + 1] = fmaf(fmaxf(c2q[mt][nl][2] + bA, 0.f), wA,
                                             fmaf(fmaxf(c2q[mt][nl][3] + bB, 0.f), wB,
                                                  px[2 * mt + 1]));
                        }
                    }
                }
            }

            #pragma unroll
            for (int i = 0; i < 4; i++) {
                px[i] += __shfl_xor_sync(0xffffffffu, px[i], 1);
                px[i] += __shfl_xor_sync(0xffffffffu, px[i], 2);
                px[i] += bx2v;
            }
            if (tm4 == 0) {
                #pragma unroll
                for (int i = 0; i < 4; i++)
                    px_sh[w * 32 + td4 + 8 * i] = px[i];
            }
            __syncwarp();
            {
                int e = w * 32 + lane;
                float p = px_sh[e];
                float sx = unit_sh[e][0] * p;
                float sy = unit_sh[e][1] * p;
                float sz = unit_sh[e][2] * p;
                #pragma unroll
                for (int o = 16; o > 0; o >>= 1) {
                    sx += __shfl_xor_sync(0xffffffffu, sx, o);
                    sy += __shfl_xor_sync(0xffffffffu, sy, o);
                    sz += __shfl_xor_sync(0xffffffffu, sz, o);
                }
                if (lane == 0) {
                    out_coords[node * 3 + 0] = coords[node * 3 + 0] + sx * (1.f / 32.f);
                    out_coords[node * 3 + 1] = coords[node * 3 + 1] + sy * (1.f / 32.f);
                    out_coords[node * 3 + 2] = coords[node * 3 + 2] + sz * (1.f / 32.f);
                }
            }
        }
        __syncthreads();
    }
}

// ---------------------------------------------------------------------------
// K3: HMMA node update.  Block 128 (4 warps), warp = 16 node-rows, grid 128.
// ---------------------------------------------------------------------------
__global__ __launch_bounds__(128) void k_node(
    const float* __restrict__ emb,
    const float* __restrict__ mask,
    const float* __restrict__ bh2g,
    float* __restrict__ out_emb)
{
    extern __shared__ unsigned char nsm[];
    const uint32_t sbn  = s2u(nsm);
    const uint32_t w2hA = sbn + OFF_W2H;
    const uint32_t wh2A = sbn + OFF_WH2;

    __shared__ float bvec_sh[128], bh2_sh[128];

    const int tid  = threadIdx.x;
    const int w    = tid >> 5;
    const int lane = tid & 31;
    const int td4  = lane >> 2;
    const int tm4  = lane & 3;

    {
        uint4* dst = (uint4*)nsm;
        for (int i = tid; i < NIMG_BYTES / 16; i += 128) dst[i] = g_Nimg[i];
    }
    if (tid < 128) {
        bvec_sh[tid] = g_bvec[tid];
        bh2_sh[tid]  = bh2g[tid];
    }
    __syncthreads();

    const int node0 = blockIdx.x * 64 + w * 16;

    float mskv[2], mscale[2];
    #pragma unroll
    for (int i = 0; i < 2; i++) {
        mskv[i]   = mask[node0 + td4 + 8 * i];
        mscale[i] = mskv[i] * (1.f / 32.f);
    }

    const int qsel  = lane >> 3;
    const int ntoff = qsel >> 1;
    const int khalf = qsel & 1;

    uint32_t a2[8][4];
    #pragma unroll
    for (int half = 0; half < 2; half++) {
        float c1h[8][4];
        #pragma unroll
        for (int nt = 0; nt < 8; nt++)
        #pragma unroll
        for (int q = 0; q < 4; q++) c1h[nt][q] = 0.f;

        #pragma unroll
        for (int kt = 0; kt < 8; kt++) {
            uint32_t af[4];
            #pragma unroll
            for (int i = 0; i < 2; i++) {
                int row = node0 + td4 + 8 * i;
                const float* hp = g_hsum + (size_t)row * 128 + kt * 16 + 2 * tm4;
                float2 va = *(const float2*)hp;
                float2 vb = *(const float2*)(hp + 8);
                float s = mscale[i];
                af[i]     = packhf(va.x * s, va.y * s);
                af[2 + i] = packhf(vb.x * s, vb.y * s);
            }
            #pragma unroll
            for (int nt2 = 0; nt2 < 4; nt2++) {
                const int ntq = half * 8 + 2 * nt2 + ntoff;
                uint32_t off = (uint32_t)((ntq * 8 + (lane & 7)) * 136
                                          + kt * 16 + khalf * 8) * 2;
                uint32_t p0, p1, p2, p3;
                ldmx4(p0, p1, p2, p3, w2hA + off);
                mma16816(c1h[2 * nt2 + 0], af, p0, p1);
                mma16816(c1h[2 * nt2 + 1], af, p2, p3);
            }
        }

        #pragma unroll
        for (int kt2l = 0; kt2l < 4; kt2l++) {
            #pragma unroll
            for (int sub = 0; sub < 2; sub++) {
                const int ntl = 2 * kt2l + sub;
                const int col = (half * 8 + ntl) * 8 + 2 * tm4;
                float2 bv2 = *(const float2*)&bvec_sh[col];
                #pragma unroll
                for (int mh = 0; mh < 2; mh++) {
                    int row = node0 + td4 + 8 * mh;
                    float2 p3v = *(const float2*)(g_p3 + (size_t)row * 128 + col);
                    float h0 = fmaxf(c1h[ntl][2 * mh + 0] + p3v.x + mskv[mh] * bv2.x, 0.f);
                    float h1 = fmaxf(c1h[ntl][2 * mh + 1] + p3v.y + mskv[mh] * bv2.y, 0.f);
                    a2[half * 4 + kt2l][mh + 2 * sub] = packhf(h0, h1);
                }
            }
        }
    }

    #pragma unroll
    for (int half = 0; half < 2; half++) {
        #pragma unroll
        for (int q4 = 0; q4 < 2; q4++) {
            float c2q[4][4];
            #pragma unroll
            for (int nl = 0; nl < 4; nl++)
            #pragma unroll
            for (int q = 0; q < 4; q++) c2q[nl][q] = 0.f;

            #pragma unroll
            for (int kt2 = 0; kt2 < 8; kt2++) {
                #pragma unroll
                for (int nl2 = 0; nl2 < 2; nl2++) {
                    const int ntq = half * 8 + q4 * 4 + 2 * nl2 + ntoff;
                    uint32_t off = (uint32_t)((ntq * 8 + (lane & 7)) * 136
                                              + kt2 * 16 + khalf * 8) * 2;
                    uint32_t p0, p1, p2, p3;
                    ldmx4(p0, p1, p2, p3, wh2A + off);
                    mma16816(c2q[2 * nl2 + 0], a2[kt2], p0, p1);
                    mma16816(c2q[2 * nl2 + 1], a2[kt2], p2, p3);
                }
            }
            #pragma unroll
            for (int nl = 0; nl < 4; nl++) {
                const int col = half * 64 + q4 * 32 + nl * 8 + 2 * tm4;
                float2 b2v = *(const float2*)&bh2_sh[col];
                #pragma unroll
                for (int mh = 0; mh < 2; mh++) {
                    int row = node0 + td4 + 8 * mh;
                    float2 ev = *(const float2*)(emb + (size_t)row * 128 + col);
                    *(float2*)(out_emb + (size_t)row * 128 + col) =
                        make_float2(ev.x + c2q[nl][2 * mh + 0] + b2v.x,
                                    ev.y + c2q[nl][2 * mh + 1] + b2v.y);
                }
            }
        }
    }
}

// ---------------------------------------------------------------------------
extern "C" void kernel_launch(void* const* d_in, const int* in_sizes, int n_in,
                              void* d_out, int out_size)
{
    const float* emb    = (const float*)d_in[0];
    const float* coords = (const float*)d_in[1];
    const float* mask   = (const float*)d_in[2];
    const float* edges  = (const float*)d_in[3];
    const float* we_w1  = (const float*)d_in[4];
    const float* we_b1  = (const float*)d_in[5];
    const float* we_w2  = (const float*)d_in[6];
    const float* we_b2  = (const float*)d_in[7];
    const float* wx_w1  = (const float*)d_in[8];
    const float* wx_b1  = (const float*)d_in[9];
    const float* wx_w2  = (const float*)d_in[10];
    const float* wx_b2  = (const float*)d_in[11];
    const float* wh_w1  = (const float*)d_in[12];
    const float* wh_b1  = (const float*)d_in[13];
    const float* wh_w2  = (const float*)d_in[14];
    const float* wh_b2  = (const float*)d_in[15];
    const int*   ids    = (const int*)d_in[16];

    float* out_emb    = (float*)d_out;
    float* out_coords = (float*)d_out + (size_t)BN * 128;

    static int attr_set = 0;
    if (!attr_set) {
        cudaFuncSetAttribute(k_edge,
                             cudaFuncAttributeMaxDynamicSharedMemorySize,
                             WIMG_BYTES);
        cudaFuncSetAttribute(k_node,
                             cudaFuncAttributeMaxDynamicSharedMemorySize,
                             NIMG_BYTES);
        cudaFuncSetAttribute(k_proj,
                             cudaFuncAttributeMaxDynamicSharedMemorySize,
                             PIMG_BYTES);
        attr_set = 1;
    }

    k_fold<<<8, 128>>>(we_w2, we_b2, wx_w1, wx_b1, wh_w1, we_w1, wh_w2);

    k_proj<<<128, 128, PIMG_BYTES>>>(emb, wh_b1);

    k_edge<<<EDGE_GRID, EDGE_THREADS, WIMG_BYTES>>>(coords, edges, we_b1,
                                                    wx_w2, wx_b2, ids, out_coords);

    k_node<<<128, 128, NIMG_BYTES>>>(emb, mask, wh_b2, out_emb);
}

// round 15
// speedup vs baseline: 1.0906x; 1.0906x over previous
#include <cuda_runtime.h>
#include <cuda_fp16.h>
#include <math.h>
#include <stdint.h>

// Problem constants
#define Bz 8
#define Nn 1024
#define Mm 32
#define BN (Bz*Nn)            // 8192
#define KFREQ (-0.6140226914650789f)   // -log(10000)/15

#define EDGE_GRID 148
#define WARPS_PER_CTA 12
#define EDGE_THREADS 384
#define NODES_PER_ITER (EDGE_GRID * WARPS_PER_CTA)   // 1776
#define NITER 5                                       // ceil(8192/1776)

// Edge weight image (bytes): B1 | B2   (plain fp16)
#define OFF_B1 0
#define OFF_B2 18432
#define WIMG_BYTES 53248

// p2 smem stage: 384 rows x 68 uint32 (64 data + 4 pad) = 104448 B
#define P2S_STRIDE 68
#define P2S_BYTES (EDGE_THREADS * P2S_STRIDE * 4)
#define EDGE_SMEM (WIMG_BYTES + P2S_BYTES)

// Proj weight image: [W1a^T | W1b^T | Wh1a^T] -> 3 x [128 n][128 k] fp16, stride 272B
#define PIMG_HALF  34816
#define PIMG_BYTES (3 * PIMG_HALF)

// Node weight image: W2h^T | Wh2^T  each [128 n][128 k] fp16, stride 272B
#define OFF_W2H 0
#define OFF_WH2 34816
#define NIMG_BYTES 69632

// ---------------------------------------------------------------------------
// Scratch
// ---------------------------------------------------------------------------
__device__ float    g_p1[BN*128];    // emb @ W1[0:128]
__device__ uint32_t g_p2h[BN*64];    // emb @ W1[128:256], packed half2
__device__ float    g_p3[BN*128];    // emb @ Wh1a + bh1
__device__ float    g_hsum[BN*128];  // sum_j relu-h
__device__ float    g_b2x[128];      // b2 @ Wx1 + bx1
__device__ float    g_bvec[128];     // b2 @ Wh1[128:256]
__device__ uint4 g_Bimg[WIMG_BYTES/16];
__device__ uint4 g_Pimg[PIMG_BYTES/16];
__device__ uint4 g_Nimg[NIMG_BYTES/16];

// ---------------------------------------------------------------------------
// helpers
// ---------------------------------------------------------------------------
__device__ __forceinline__ uint32_t s2u(const void* p) {
    uint32_t a;
    asm("{ .reg .u64 t; cvta.to.shared.u64 t, %1; cvt.u32.u64 %0, t; }"
        : "=r"(a) : "l"(p));
    return a;
}
__device__ __forceinline__ void ldmx4(uint32_t& r0, uint32_t& r1,
                                      uint32_t& r2, uint32_t& r3, uint32_t addr) {
    asm volatile("ldmatrix.sync.aligned.m8n8.x4.shared.b16 {%0,%1,%2,%3}, [%4];"
                 : "=r"(r0), "=r"(r1), "=r"(r2), "=r"(r3) : "r"(addr));
}
__device__ __forceinline__ void mma16816(float* c, const uint32_t* a,
                                         uint32_t b0, uint32_t b1) {
    asm volatile(
        "mma.sync.aligned.m16n8k16.row.col.f32.f16.f16.f32 "
        "{%0,%1,%2,%3}, {%4,%5,%6,%7}, {%8,%9}, {%0,%1,%2,%3};"
        : "+f"(c[0]), "+f"(c[1]), "+f"(c[2]), "+f"(c[3])
        : "r"(a[0]), "r"(a[1]), "r"(a[2]), "r"(a[3]), "r"(b0), "r"(b1));
}
// pack: lower half = f0, upper = f1
__device__ __forceinline__ uint32_t packhf(float f0, float f1) {
    uint32_t r;
    asm("cvt.rn.f16x2.f32 %0, %1, %2;" : "=r"(r) : "f"(f1), "f"(f0));
    return r;
}
__device__ __forceinline__ float2 unpackhf(uint32_t v) {
    __half2 h = *(__half2*)&v;
    return __half22float2(h);
}

// ---------------------------------------------------------------------------
// K-1: fold + all weight-image prep.
// ---------------------------------------------------------------------------
__global__ __launch_bounds__(128) void k_fold(
    const float* __restrict__ w2,  const float* __restrict__ b2,
    const float* __restrict__ wx1, const float* __restrict__ bx1,
    const float* __restrict__ wh1, const float* __restrict__ w1,
    const float* __restrict__ wh2)
{
    __shared__ float w2sh[16][128];
    unsigned char* img  = (unsigned char*)g_Bimg;
    unsigned char* img2 = (unsigned char*)g_Pimg;
    unsigned char* img3 = (unsigned char*)g_Nimg;
    const int c = threadIdx.x;
    const int d0 = blockIdx.x * 16;

    #pragma unroll
    for (int i = 0; i < 16; i++)
        w2sh[i][c] = w2[(d0 + i) * 128 + c];
    __syncthreads();

    float a1[16], a2[16];
    #pragma unroll
    for (int i = 0; i < 16; i++) { a1[i] = 0.f; a2[i] = 0.f; }

    #pragma unroll 2
    for (int k = 0; k < 128; k++) {
        float wA = wx1[k * 128 + c];
        float wB = wh1[(128 + k) * 128 + c];
        #pragma unroll
        for (int i = 0; i < 16; i++) {
            float v = w2sh[i][k];
            a1[i] = fmaf(v, wA, a1[i]);
            a2[i] = fmaf(v, wB, a2[i]);
        }
    }
    #pragma unroll
    for (int i = 0; i < 16; i++) {
        *(__half*)(img + OFF_B2 + (uint32_t)c * 272 + (uint32_t)(d0 + i) * 2)
            = __float2half_rn(a1[i]);
        *(__half*)(img3 + OFF_W2H + (uint32_t)c * 272 + (uint32_t)(d0 + i) * 2)
            = __float2half_rn(a2[i]);
    }

    // B1 image
    #pragma unroll
    for (int j = 0; j < 8; j++) {
        int e = blockIdx.x * 1024 + j * 128 + c;
        int n = e & 127, k = e >> 7;
        *(__half*)(img + OFF_B1 + (uint32_t)n * 144 + (uint32_t)k * 2)
            = __float2half_rn(w1[(256 + k) * 128 + n]);
    }

    // Proj image: n<256: W1ab^T;  n>=256: Wh1a^T
    #pragma unroll
    for (int j = 0; j < 48; j++) {
        int e = blockIdx.x * 6144 + j * 128 + c;
        int k = e / 384;
        int n = e - k * 384;
        float v = (n < 256) ? w1[(k + ((n >> 7) << 7)) * 128 + (n & 127)]
                            : wh1[k * 128 + (n - 256)];
        *(__half*)(img2 + (uint32_t)n * 272 + (uint32_t)k * 2)
            = __float2half_rn(v);
    }

    // Wh2 image
    #pragma unroll
    for (int j = 0; j < 16; j++) {
        int e = blockIdx.x * 2048 + j * 128 + c;
        int n = e & 127, k = e >> 7;
        *(__half*)(img3 + OFF_WH2 + (uint32_t)n * 272 + (uint32_t)k * 2)
            = __float2half_rn(wh2[k * 128 + n]);
    }

    if (blockIdx.x == 0) {
        float s1 = bx1[c], s2 = 0.f;
        for (int k = 0; k < 128; k++) {
            float bk = b2[k];
            s1 = fmaf(bk, wx1[k * 128 + c], s1);
            s2 = fmaf(bk, wh1[(128 + k) * 128 + c], s2);
        }
        g_b2x[c]  = s1;
        g_bvec[c] = s2;
    }
}

// ---------------------------------------------------------------------------
// K0: HMMA projection.  grid (64, 3): x = 128-node group, y = {p1,p2,p3}.
// p2 is stored packed fp16; p3 gets +bh1.   (R13-validated version)
// ---------------------------------------------------------------------------
__global__ __launch_bounds__(128) void k_proj(
    const float* __restrict__ emb, const float* __restrict__ bh1g)
{
    extern __shared__ unsigned char psm[];
    const uint32_t sbp = s2u(psm);

    const int tid  = threadIdx.x;
    const int w    = tid >> 5;
    const int lane = tid & 31;
    const int td4  = lane >> 2;
    const int tm4  = lane & 3;
    const int half = blockIdx.y;

    {
        uint4* dst = (uint4*)psm;
        const uint4* src = g_Pimg + (size_t)half * (PIMG_HALF / 16);
        for (int i = tid; i < PIMG_HALF / 16; i += 128) dst[i] = src[i];
    }
    __syncthreads();

    const int node = blockIdx.x * 128 + w * 32;

    uint32_t af[8][2][4];
    #pragma unroll
    for (int kt = 0; kt < 8; kt++) {
        #pragma unroll
        for (int i = 0; i < 4; i++) {
            int row = node + td4 + 8 * i;
            const float* ep = emb + (size_t)row * 128 + kt * 16 + 2 * tm4;
            float2 va = *(const float2*)ep;
            float2 vb = *(const float2*)(ep + 8);
            int mt = i >> 1, s = i & 1;
            af[kt][mt][s]     = packhf(va.x, va.y);
            af[kt][mt][2 + s] = packhf(vb.x, vb.y);
        }
    }

    const int qsel  = lane >> 3;
    const int ntoff = qsel >> 1;
    const int khalf = qsel & 1;

    #pragma unroll
    for (int chunk = 0; chunk < 2; chunk++) {
        float cc[2][8][4];
        #pragma unroll
        for (int mt = 0; mt < 2; mt++)
        #pragma unroll
        for (int nt = 0; nt < 8; nt++)
        #pragma unroll
        for (int q = 0; q < 4; q++) cc[mt][nt][q] = 0.f;

        #pragma unroll
        for (int kt = 0; kt < 8; kt++) {
            #pragma unroll
            for (int nt2 = 0; nt2 < 4; nt2++) {
                const int ntq = chunk * 8 + 2 * nt2 + ntoff;
                uint32_t off = (uint32_t)((ntq * 8 + (lane & 7)) * 136
                                          + kt * 16 + khalf * 8) * 2;
                uint32_t p0, p1, p2, p3;
                ldmx4(p0, p1, p2, p3, sbp + off);
                #pragma unroll
                for (int mt = 0; mt < 2; mt++) {
                    mma16816(cc[mt][2 * nt2 + 0], af[kt][mt], p0, p1);
                    mma16816(cc[mt][2 * nt2 + 1], af[kt][mt], p2, p3);
                }
            }
        }
        #pragma unroll
        for (int ntl = 0; ntl < 8; ntl++) {
            const int col = (chunk * 8 + ntl) * 8 + 2 * tm4;
            float2 bb = make_float2(0.f, 0.f);
            if (half == 2) bb = *(const float2*)(bh1g + col);
            #pragma unroll
            for (int mt = 0; mt < 2; mt++) {
                #pragma unroll
                for (int mh = 0; mh < 2; mh++) {
                    int row = node + td4 + 8 * (2 * mt + mh);
                    float v0 = cc[mt][ntl][2 * mh + 0] + bb.x;
                    float v1 = cc[mt][ntl][2 * mh + 1] + bb.y;
                    if (half == 0)
                        *(float2*)(g_p1 + (size_t)row * 128 + col) = make_float2(v0, v1);
                    else if (half == 1)
                        g_p2h[(size_t)row * 64 + (col >> 1)] = packhf(v0, v1);
                    else
                        *(float2*)(g_p3 + (size_t)row * 128 + col) = make_float2(v0, v1);
                }
            }
        }
    }
}

// ---------------------------------------------------------------------------
// K1: HMMA edge kernel.  384 threads (12 warps), warp = node.
// p2 rows staged cooperatively into smem before the GEMMs (latency hiding).
// ---------------------------------------------------------------------------
__global__ __launch_bounds__(EDGE_THREADS, 1) void k_edge(
    const float* __restrict__ coords,
    const float* __restrict__ edges,
    const float* __restrict__ b1g,
    const float* __restrict__ wx2, const float* __restrict__ bx2,
    const int* __restrict__ ids,
    float* __restrict__ out_coords)
{
    extern __shared__ unsigned char wsm[];
    const uint32_t sb  = s2u(wsm);
    const uint32_t b1A = sb + OFF_B1;
    const uint32_t b2A = sb + OFF_B2;
    uint32_t* p2s = (uint32_t*)(wsm + WIMG_BYTES);   // [384][P2S_STRIDE]

    __shared__ float dist_sh[EDGE_THREADS];
    __shared__ float unit_sh[EDGE_THREADS][3];
    __shared__ int   jid_sh[EDGE_THREADS];
    __shared__ float px_sh[EDGE_THREADS];
    __shared__ float b1_sh[128], b2x_sh[128], wx2_sh[128], fr_sh[16];

    const int tid  = threadIdx.x;
    const int w    = tid >> 5;
    const int lane = tid & 31;
    const int td4  = lane >> 2;
    const int tm4  = lane & 3;

    {
        uint4* dst = (uint4*)wsm;
        for (int i = tid; i < WIMG_BYTES / 16; i += EDGE_THREADS) dst[i] = g_Bimg[i];
    }
    if (tid < 128) {
        b1_sh[tid]  = b1g[tid];
        b2x_sh[tid] = g_b2x[tid];
        wx2_sh[tid] = wx2[tid];
    }
    if (tid < 16) fr_sh[tid] = expf((float)tid * KFREQ);
    __syncthreads();

    const float fr0 = fr_sh[2 * tm4],     fr1 = fr_sh[2 * tm4 + 1];
    const float fr2 = fr_sh[2 * tm4 + 8], fr3 = fr_sh[2 * tm4 + 9];
    const float bx2v = bx2[0];

    const int qsel  = lane >> 3;
    const int ntoff = qsel >> 1;
    const int khalf = qsel & 1;

    for (int it = 0; it < NITER; it++) {
        const int nodebase = it * NODES_PER_ITER + blockIdx.x * WARPS_PER_CTA;

        {
            int nd = nodebase + (tid >> 5);
            if (nd < BN) {
                int m = tid & 31;
                int jabs = ((nd >> 10) << 10) + ids[nd * 32 + m];
                jid_sh[tid] = jabs;
                float dx = coords[nd * 3 + 0] - coords[jabs * 3 + 0];
                float dy = coords[nd * 3 + 1] - coords[jabs * 3 + 1];
                float dz = coords[nd * 3 + 2] - coords[jabs * 3 + 2];
                float d = sqrtf(dx * dx + dy * dy + dz * dz);
                dist_sh[tid] = d;
                float inv = (d > 0.f) ? (1.f / d) : 0.f;
                unit_sh[tid][0] = dx * inv;
                unit_sh[tid][1] = dy * inv;
                unit_sh[tid][2] = dz * inv;
            }
        }
        __syncthreads();

        // --- stage p2 rows for all 384 edges (coalesced uint4, 16/thread) ---
        {
            #pragma unroll
            for (int i = 0; i < 16; i++) {
                int idx = i * EDGE_THREADS + tid;
                int e = idx >> 4, part = idx & 15;
                int nd = nodebase + (e >> 5);
                if (nd < BN) {
                    const uint4* src = (const uint4*)(g_p2h + (size_t)jid_sh[e] * 64);
                    *(uint4*)(p2s + e * P2S_STRIDE + part * 4) = src[part];
                }
            }
        }
        __syncthreads();

        const int node = nodebase + w;
        if (node < BN) {
            float dloc[4];
            #pragma unroll
            for (int i = 0; i < 4; i++) dloc[i] = dist_sh[w * 32 + td4 + 8 * i];

            uint32_t ahi[4][2][4];
            #pragma unroll
            for (int kt = 0; kt < 4; kt++) {
                #pragma unroll
                for (int i = 0; i < 4; i++) {
                    float v0, v1, v2, v3;
                    if (kt == 0) {
                        v0 = __sinf(dloc[i] * fr0); v1 = __sinf(dloc[i] * fr1);
                        v2 = __sinf(dloc[i] * fr2); v3 = __sinf(dloc[i] * fr3);
                    } else if (kt == 1) {
                        v0 = __cosf(dloc[i] * fr0); v1 = __cosf(dloc[i] * fr1);
                        v2 = __cosf(dloc[i] * fr2); v3 = __cosf(dloc[i] * fr3);
                    } else {
                        const float* ep = edges
                            + (size_t)(node * 32 + td4 + 8 * i) * 32
                            + (kt - 2) * 16 + 2 * tm4;
                        float2 va = *(const float2*)ep;
                        float2 vb = *(const float2*)(ep + 8);
                        v0 = va.x; v1 = va.y; v2 = vb.x; v3 = vb.y;
                    }
                    int mt = i >> 1, s = i & 1;
                    ahi[kt][mt][s]     = packhf(v0, v1);
                    ahi[kt][mt][2 + s] = packhf(v2, v3);
                }
            }

            uint32_t a2[2][8][4];
            #pragma unroll
            for (int half = 0; half < 2; half++) {
                float c1h[2][8][4];
                #pragma unroll
                for (int mt = 0; mt < 2; mt++)
                #pragma unroll
                for (int nt = 0; nt < 8; nt++)
                #pragma unroll
                for (int q = 0; q < 4; q++) c1h[mt][nt][q] = 0.f;

                #pragma unroll
                for (int kt = 0; kt < 4; kt++) {
                    #pragma unroll
                    for (int nt2 = 0; nt2 < 4; nt2++) {
                        const int ntq = half * 8 + 2 * nt2 + ntoff;
                        uint32_t off = (uint32_t)((ntq * 8 + (lane & 7)) * 72
                                                  + kt * 16 + khalf * 8) * 2;
                        uint32_t p0, p1, p2, p3;
                        ldmx4(p0, p1, p2, p3, b1A + off);
                        #pragma unroll
                        for (int mt = 0; mt < 2; mt++) {
                            mma16816(c1h[mt][2 * nt2 + 0], ahi[kt][mt], p0, p1);
                            mma16816(c1h[mt][2 * nt2 + 1], ahi[kt][mt], p2, p3);
                        }
                    }
                }

                #pragma unroll
                for (int kt2l = 0; kt2l < 4; kt2l++) {
                    #pragma unroll
                    for (int sub = 0; sub < 2; sub++) {
                        const int ntl = 2 * kt2l + sub;
                        const int n0c = (half * 8 + ntl) * 8 + 2 * tm4;
                        float2 pa = *(const float2*)(g_p1 + (size_t)node * 128 + n0c);
                        const float bb0 = b1_sh[n0c], bb1 = b1_sh[n0c + 1];
                        float hs0 = 0.f, hs1 = 0.f;
                        #pragma unroll
                        for (int mt = 0; mt < 2; mt++) {
                            #pragma unroll
                            for (int mh = 0; mh < 2; mh++) {
                                int e = w * 32 + td4 + 8 * (2 * mt + mh);
                                float2 p2v = unpackhf(p2s[e * P2S_STRIDE + (n0c >> 1)]);
                                float h0 = fmaxf(c1h[mt][ntl][2 * mh + 0] + pa.x + p2v.x + bb0, 0.f);
                                float h1 = fmaxf(c1h[mt][ntl][2 * mh + 1] + pa.y + p2v.y + bb1, 0.f);
                                hs0 += h0; hs1 += h1;
                                a2[mt][half * 4 + kt2l][mh + 2 * sub] = packhf(h0, h1);
                            }
                        }
                        #pragma unroll
                        for (int o = 4; o < 32; o <<= 1) {
                            hs0 += __shfl_xor_sync(0xffffffffu, hs0, o);
                            hs1 += __shfl_xor_sync(0xffffffffu, hs1, o);
                        }
                        if (td4 == 0) {
                            g_hsum[(size_t)node * 128 + n0c]     = hs0;
                            g_hsum[(size_t)node * 128 + n0c + 1] = hs1;
                        }
                    }
                }
            }

            float px[4] = {0.f, 0.f, 0.f, 0.f};
            #pragma unroll
            for (int half = 0; half < 2; half++) {
                #pragma unroll
                for (int q4 = 0; q4 < 2; q4++) {
                    float c2q[2][4][4];
                    #pragma unroll
                    for (int mt = 0; mt < 2; mt++)
                    #pragma unroll
                    for (int nl = 0; nl < 4; nl++)
                    #pragma unroll
                    for (int q = 0; q < 4; q++) c2q[mt][nl][q] = 0.f;

                    #pragma unroll
                    for (int kt2 = 0; kt2 < 8; kt2++) {
                        #pragma unroll
                        for (int nl2 = 0; nl2 < 2; nl2++) {
                            const int ntq = half * 8 + q4 * 4 + 2 * nl2 + ntoff;
                            uint32_t off = (uint32_t)((ntq * 8 + (lane & 7)) * 136
                                                      + kt2 * 16 + khalf * 8) * 2;
                            uint32_t p0, p1, p2, p3;
                            ldmx4(p0, p1, p2, p3, b2A + off);
                            #pragma unroll
                            for (int mt = 0; mt < 2; mt++) {
                                mma16816(c2q[mt][2 * nl2 + 0], a2[mt][kt2], p0, p1);
                                mma16816(c2q[mt][2 * nl2 + 1], a2[mt][kt2], p2, p3);
                            }
                        }
                    }
                    #pragma unroll
                    for (int nl = 0; nl < 4; nl++) {
                        const int n = half * 64 + q4 * 32 + nl * 8 + 2 * tm4;
                        const float bA = b2x_sh[n], bB = b2x_sh[n + 1];
                        const float wA = wx2_sh[n], wB = wx2_sh[n + 1];
                        #pragma unroll
                        for (int mt = 0; mt < 2; mt++) {
                            px[2 * mt + 0] = fmaf(fmaxf(c2q[mt][nl][0] + bA, 0.f), wA,
                                             fmaf(fmaxf(c2q[mt][nl][1] + bB, 0.f), wB,
                                                  px[2 * mt + 0]));
                            px[2 * mt + 1] = fmaf(fmaxf(c2q[mt][nl][2] + bA, 0.f), wA,
                                             fmaf(fmaxf(c2q[mt][nl][3] + bB, 0.f), wB,
                                                  px[2 * mt + 1]));
                        }
                    }
                }
            }

            #pragma unroll
            for (int i = 0; i < 4; i++) {
                px[i] += __shfl_xor_sync(0xffffffffu, px[i], 1);
                px[i] += __shfl_xor_sync(0xffffffffu, px[i], 2);
                px[i] += bx2v;
            }
            if (tm4 == 0) {
                #pragma unroll
                for (int i = 0; i < 4; i++)
                    px_sh[w * 32 + td4 + 8 * i] = px[i];
            }
            __syncwarp();
            {
                int e = w * 32 + lane;
                float p = px_sh[e];
                float sx = unit_sh[e][0] * p;
                float sy = unit_sh[e][1] * p;
                float sz = unit_sh[e][2] * p;
                #pragma unroll
                for (int o = 16; o > 0; o >>= 1) {
                    sx += __shfl_xor_sync(0xffffffffu, sx, o);
                    sy += __shfl_xor_sync(0xffffffffu, sy, o);
                    sz += __shfl_xor_sync(0xffffffffu, sz, o);
                }
                if (lane == 0) {
                    out_coords[node * 3 + 0] = coords[node * 3 + 0] + sx * (1.f / 32.f);
                    out_coords[node * 3 + 1] = coords[node * 3 + 1] + sy * (1.f / 32.f);
                    out_coords[node * 3 + 2] = coords[node * 3 + 2] + sz * (1.f / 32.f);
                }
            }
        }
        __syncthreads();
    }
}

// ---------------------------------------------------------------------------
// K3: HMMA node update.  Block 128 (4 warps), warp = 16 node-rows, grid 128.
// ---------------------------------------------------------------------------
__global__ __launch_bounds__(128) void k_node(
    const float* __restrict__ emb,
    const float* __restrict__ mask,
    const float* __restrict__ bh2g,
    float* __restrict__ out_emb)
{
    extern __shared__ unsigned char nsm[];
    const uint32_t sbn  = s2u(nsm);
    const uint32_t w2hA = sbn + OFF_W2H;
    const uint32_t wh2A = sbn + OFF_WH2;

    __shared__ float bvec_sh[128], bh2_sh[128];

    const int tid  = threadIdx.x;
    const int w    = tid >> 5;
    const int lane = tid & 31;
    const int td4  = lane >> 2;
    const int tm4  = lane & 3;

    {
        uint4* dst = (uint4*)nsm;
        for (int i = tid; i < NIMG_BYTES / 16; i += 128) dst[i] = g_Nimg[i];
    }
    if (tid < 128) {
        bvec_sh[tid] = g_bvec[tid];
        bh2_sh[tid]  = bh2g[tid];
    }
    __syncthreads();

    const int node0 = blockIdx.x * 64 + w * 16;

    float mskv[2], mscale[2];
    #pragma unroll
    for (int i = 0; i < 2; i++) {
        mskv[i]   = mask[node0 + td4 + 8 * i];
        mscale[i] = mskv[i] * (1.f / 32.f);
    }

    const int qsel  = lane >> 3;
    const int ntoff = qsel >> 1;
    const int khalf = qsel & 1;

    uint32_t a2[8][4];
    #pragma unroll
    for (int half = 0; half < 2; half++) {
        float c1h[8][4];
        #pragma unroll
        for (int nt = 0; nt < 8; nt++)
        #pragma unroll
        for (int q = 0; q < 4; q++) c1h[nt][q] = 0.f;

        #pragma unroll
        for (int kt = 0; kt < 8; kt++) {
            uint32_t af[4];
            #pragma unroll
            for (int i = 0; i < 2; i++) {
                int row = node0 + td4 + 8 * i;
                const float* hp = g_hsum + (size_t)row * 128 + kt * 16 + 2 * tm4;
                float2 va = *(const float2*)hp;
                float2 vb = *(const float2*)(hp + 8);
                float s = mscale[i];
                af[i]     = packhf(va.x * s, va.y * s);
                af[2 + i] = packhf(vb.x * s, vb.y * s);
            }
            #pragma unroll
            for (int nt2 = 0; nt2 < 4; nt2++) {
                const int ntq = half * 8 + 2 * nt2 + ntoff;
                uint32_t off = (uint32_t)((ntq * 8 + (lane & 7)) * 136
                                          + kt * 16 + khalf * 8) * 2;
                uint32_t p0, p1, p2, p3;
                ldmx4(p0, p1, p2, p3, w2hA + off);
                mma16816(c1h[2 * nt2 + 0], af, p0, p1);
                mma16816(c1h[2 * nt2 + 1], af, p2, p3);
            }
        }

        #pragma unroll
        for (int kt2l = 0; kt2l < 4; kt2l++) {
            #pragma unroll
            for (int sub = 0; sub < 2; sub++) {
                const int ntl = 2 * kt2l + sub;
                const int col = (half * 8 + ntl) * 8 + 2 * tm4;
                float2 bv2 = *(const float2*)&bvec_sh[col];
                #pragma unroll
                for (int mh = 0; mh < 2; mh++) {
                    int row = node0 + td4 + 8 * mh;
                    float2 p3v = *(const float2*)(g_p3 + (size_t)row * 128 + col);
                    float h0 = fmaxf(c1h[ntl][2 * mh + 0] + p3v.x + mskv[mh] * bv2.x, 0.f);
                    float h1 = fmaxf(c1h[ntl][2 * mh + 1] + p3v.y + mskv[mh] * bv2.y, 0.f);
                    a2[half * 4 + kt2l][mh + 2 * sub] = packhf(h0, h1);
                }
            }
        }
    }

    #pragma unroll
    for (int half = 0; half < 2; half++) {
        #pragma unroll
        for (int q4 = 0; q4 < 2; q4++) {
            float c2q[4][4];
            #pragma unroll
            for (int nl = 0; nl < 4; nl++)
            #pragma unroll
            for (int q = 0; q < 4; q++) c2q[nl][q] = 0.f;

            #pragma unroll
            for (int kt2 = 0; kt2 < 8; kt2++) {
                #pragma unroll
                for (int nl2 = 0; nl2 < 2; nl2++) {
                    const int ntq = half * 8 + q4 * 4 + 2 * nl2 + ntoff;
                    uint32_t off = (uint32_t)((ntq * 8 + (lane & 7)) * 136
                                              + kt2 * 16 + khalf * 8) * 2;
                    uint32_t p0, p1, p2, p3;
                    ldmx4(p0, p1, p2, p3, wh2A + off);
                    mma16816(c2q[2 * nl2 + 0], a2[kt2], p0, p1);
                    mma16816(c2q[2 * nl2 + 1], a2[kt2], p2, p3);
                }
            }
            #pragma unroll
            for (int nl = 0; nl < 4; nl++) {
                const int col = half * 64 + q4 * 32 + nl * 8 + 2 * tm4;
                float2 b2v = *(const float2*)&bh2_sh[col];
                #pragma unroll
                for (int mh = 0; mh < 2; mh++) {
                    int row = node0 + td4 + 8 * mh;
                    float2 ev = *(const float2*)(emb + (size_t)row * 128 + col);
                    *(float2*)(out_emb + (size_t)row * 128 + col) =
                        make_float2(ev.x + c2q[nl][2 * mh + 0] + b2v.x,
                                    ev.y + c2q[nl][2 * mh + 1] + b2v.y);
                }
            }
        }
    }
}

// ---------------------------------------------------------------------------
extern "C" void kernel_launch(void* const* d_in, const int* in_sizes, int n_in,
                              void* d_out, int out_size)
{
    const float* emb    = (const float*)d_in[0];
    const float* coords = (const float*)d_in[1];
    const float* mask   = (const float*)d_in[2];
    const float* edges  = (const float*)d_in[3];
    const float* we_w1  = (const float*)d_in[4];
    const float* we_b1  = (const float*)d_in[5];
    const float* we_w2  = (const float*)d_in[6];
    const float* we_b2  = (const float*)d_in[7];
    const float* wx_w1  = (const float*)d_in[8];
    const float* wx_b1  = (const float*)d_in[9];
    const float* wx_w2  = (const float*)d_in[10];
    const float* wx_b2  = (const float*)d_in[11];
    const float* wh_w1  = (const float*)d_in[12];
    const float* wh_b1  = (const float*)d_in[13];
    const float* wh_w2  = (const float*)d_in[14];
    const float* wh_b2  = (const float*)d_in[15];
    const int*   ids    = (const int*)d_in[16];

    float* out_emb    = (float*)d_out;
    float* out_coords = (float*)d_out + (size_t)BN * 128;

    static int attr_set = 0;
    if (!attr_set) {
        cudaFuncSetAttribute(k_edge,
                             cudaFuncAttributeMaxDynamicSharedMemorySize,
                             EDGE_SMEM);
        cudaFuncSetAttribute(k_node,
                             cudaFuncAttributeMaxDynamicSharedMemorySize,
                             NIMG_BYTES);
        attr_set = 1;
    }

    k_fold<<<8, 128>>>(we_w2, we_b2, wx_w1, wx_b1, wh_w1, we_w1, wh_w2);

    dim3 pg(64, 3);
    k_proj<<<pg, 128, PIMG_HALF>>>(emb, wh_b1);

    k_edge<<<EDGE_GRID, EDGE_THREADS, EDGE_SMEM>>>(coords, edges, we_b1,
                                                   wx_w2, wx_b2, ids, out_coords);

    k_node<<<128, 128, NIMG_BYTES>>>(emb, mask, wh_b2, out_emb);
}

// round 16
// speedup vs baseline: 1.1811x; 1.0830x over previous
#include <cuda_runtime.h>
#include <cuda_fp16.h>
#include <math.h>
#include <stdint.h>

// Problem constants
#define Bz 8
#define Nn 1024
#define Mm 32
#define BN (Bz*Nn)            // 8192
#define KFREQ (-0.6140226914650789f)   // -log(10000)/15

#define EDGE_GRID 148
#define WARPS_PER_CTA 12
#define NODES_PER_ITER (EDGE_GRID * WARPS_PER_CTA)   // 1776
#define NITER 5                                       // ceil(8192/1776)

// Edge weight image (bytes): B1 | B2   (plain fp16)
#define OFF_B1 0
#define OFF_B2 18432
#define WIMG_BYTES 53248

// Proj weight image: [W1a^T | W1b^T | Wh1a^T] -> 3 x [128 n][128 k] fp16, stride 272B
#define PIMG_HALF  34816
#define PIMG_BYTES (3 * PIMG_HALF)

// Node weight image: W2h^T | Wh2^T  each [128 n][128 k] fp16, stride 272B
#define OFF_W2H 0
#define OFF_WH2 34816
#define NIMG_BYTES 69632

// ---------------------------------------------------------------------------
// Scratch
// ---------------------------------------------------------------------------
__device__ float    g_p1[BN*128];    // emb @ W1[0:128]
__device__ uint32_t g_p2h[BN*64];    // emb @ W1[128:256], packed half2
__device__ float    g_p3[BN*128];    // emb @ Wh1a + bh1
__device__ float    g_hsum[BN*128];  // sum_j relu-h
__device__ float    g_b2x[128];      // b2 @ Wx1 + bx1
__device__ float    g_bvec[128];     // b2 @ Wh1[128:256]
__device__ uint4 g_Bimg[WIMG_BYTES/16];
__device__ uint4 g_Pimg[PIMG_BYTES/16];
__device__ uint4 g_Nimg[NIMG_BYTES/16];

// ---------------------------------------------------------------------------
// helpers
// ---------------------------------------------------------------------------
__device__ __forceinline__ uint32_t s2u(const void* p) {
    uint32_t a;
    asm("{ .reg .u64 t; cvta.to.shared.u64 t, %1; cvt.u32.u64 %0, t; }"
        : "=r"(a) : "l"(p));
    return a;
}
__device__ __forceinline__ void ldmx4(uint32_t& r0, uint32_t& r1,
                                      uint32_t& r2, uint32_t& r3, uint32_t addr) {
    asm volatile("ldmatrix.sync.aligned.m8n8.x4.shared.b16 {%0,%1,%2,%3}, [%4];"
                 : "=r"(r0), "=r"(r1), "=r"(r2), "=r"(r3) : "r"(addr));
}
__device__ __forceinline__ void mma16816(float* c, const uint32_t* a,
                                         uint32_t b0, uint32_t b1) {
    asm volatile(
        "mma.sync.aligned.m16n8k16.row.col.f32.f16.f16.f32 "
        "{%0,%1,%2,%3}, {%4,%5,%6,%7}, {%8,%9}, {%0,%1,%2,%3};"
        : "+f"(c[0]), "+f"(c[1]), "+f"(c[2]), "+f"(c[3])
        : "r"(a[0]), "r"(a[1]), "r"(a[2]), "r"(a[3]), "r"(b0), "r"(b1));
}
// pack: lower half = f0, upper = f1
__device__ __forceinline__ uint32_t packhf(float f0, float f1) {
    uint32_t r;
    asm("cvt.rn.f16x2.f32 %0, %1, %2;" : "=r"(r) : "f"(f1), "f"(f0));
    return r;
}
__device__ __forceinline__ float2 unpackhf(uint32_t v) {
    __half2 h = *(__half2*)&v;
    return __half22float2(h);
}

// ---------------------------------------------------------------------------
// K-1: fold + all weight-image prep.
// ---------------------------------------------------------------------------
__global__ __launch_bounds__(128) void k_fold(
    const float* __restrict__ w2,  const float* __restrict__ b2,
    const float* __restrict__ wx1, const float* __restrict__ bx1,
    const float* __restrict__ wh1, const float* __restrict__ w1,
    const float* __restrict__ wh2)
{
    __shared__ float w2sh[16][128];
    unsigned char* img  = (unsigned char*)g_Bimg;
    unsigned char* img2 = (unsigned char*)g_Pimg;
    unsigned char* img3 = (unsigned char*)g_Nimg;
    const int c = threadIdx.x;
    const int d0 = blockIdx.x * 16;

    #pragma unroll
    for (int i = 0; i < 16; i++)
        w2sh[i][c] = w2[(d0 + i) * 128 + c];
    __syncthreads();

    float a1[16], a2[16];
    #pragma unroll
    for (int i = 0; i < 16; i++) { a1[i] = 0.f; a2[i] = 0.f; }

    #pragma unroll 2
    for (int k = 0; k < 128; k++) {
        float wA = wx1[k * 128 + c];
        float wB = wh1[(128 + k) * 128 + c];
        #pragma unroll
        for (int i = 0; i < 16; i++) {
            float v = w2sh[i][k];
            a1[i] = fmaf(v, wA, a1[i]);
            a2[i] = fmaf(v, wB, a2[i]);
        }
    }
    #pragma unroll
    for (int i = 0; i < 16; i++) {
        *(__half*)(img + OFF_B2 + (uint32_t)c * 272 + (uint32_t)(d0 + i) * 2)
            = __float2half_rn(a1[i]);
        *(__half*)(img3 + OFF_W2H + (uint32_t)c * 272 + (uint32_t)(d0 + i) * 2)
            = __float2half_rn(a2[i]);
    }

    // B1 image
    #pragma unroll
    for (int j = 0; j < 8; j++) {
        int e = blockIdx.x * 1024 + j * 128 + c;
        int n = e & 127, k = e >> 7;
        *(__half*)(img + OFF_B1 + (uint32_t)n * 144 + (uint32_t)k * 2)
            = __float2half_rn(w1[(256 + k) * 128 + n]);
    }

    // Proj image: n<256: W1ab^T;  n>=256: Wh1a^T
    #pragma unroll
    for (int j = 0; j < 48; j++) {
        int e = blockIdx.x * 6144 + j * 128 + c;
        int k = e / 384;
        int n = e - k * 384;
        float v = (n < 256) ? w1[(k + ((n >> 7) << 7)) * 128 + (n & 127)]
                            : wh1[k * 128 + (n - 256)];
        *(__half*)(img2 + (uint32_t)n * 272 + (uint32_t)k * 2)
            = __float2half_rn(v);
    }

    // Wh2 image
    #pragma unroll
    for (int j = 0; j < 16; j++) {
        int e = blockIdx.x * 2048 + j * 128 + c;
        int n = e & 127, k = e >> 7;
        *(__half*)(img3 + OFF_WH2 + (uint32_t)n * 272 + (uint32_t)k * 2)
            = __float2half_rn(wh2[k * 128 + n]);
    }

    if (blockIdx.x == 0) {
        float s1 = bx1[c], s2 = 0.f;
        for (int k = 0; k < 128; k++) {
            float bk = b2[k];
            s1 = fmaf(bk, wx1[k * 128 + c], s1);
            s2 = fmaf(bk, wh1[(128 + k) * 128 + c], s2);
        }
        g_b2x[c]  = s1;
        g_bvec[c] = s2;
    }
}

// ---------------------------------------------------------------------------
// K0: HMMA projection.  grid (64, 3): x = 128-node group, y = {p1,p2,p3}.
// p2 is stored packed fp16; p3 gets +bh1.
// ---------------------------------------------------------------------------
__global__ __launch_bounds__(128) void k_proj(
    const float* __restrict__ emb, const float* __restrict__ bh1g)
{
    extern __shared__ unsigned char psm[];
    const uint32_t sbp = s2u(psm);

    const int tid  = threadIdx.x;
    const int w    = tid >> 5;
    const int lane = tid & 31;
    const int td4  = lane >> 2;
    const int tm4  = lane & 3;
    const int half = blockIdx.y;

    {
        uint4* dst = (uint4*)psm;
        const uint4* src = g_Pimg + (size_t)half * (PIMG_HALF / 16);
        for (int i = tid; i < PIMG_HALF / 16; i += 128) dst[i] = src[i];
    }
    __syncthreads();

    const int node = blockIdx.x * 128 + w * 32;

    uint32_t af[8][2][4];
    #pragma unroll
    for (int kt = 0; kt < 8; kt++) {
        #pragma unroll
        for (int i = 0; i < 4; i++) {
            int row = node + td4 + 8 * i;
            const float* ep = emb + (size_t)row * 128 + kt * 16 + 2 * tm4;
            float2 va = *(const float2*)ep;
            float2 vb = *(const float2*)(ep + 8);
            int mt = i >> 1, s = i & 1;
            af[kt][mt][s]     = packhf(va.x, va.y);
            af[kt][mt][2 + s] = packhf(vb.x, vb.y);
        }
    }

    const int qsel  = lane >> 3;
    const int ntoff = qsel >> 1;
    const int khalf = qsel & 1;

    #pragma unroll
    for (int chunk = 0; chunk < 2; chunk++) {
        float cc[2][8][4];
        #pragma unroll
        for (int mt = 0; mt < 2; mt++)
        #pragma unroll
        for (int nt = 0; nt < 8; nt++)
        #pragma unroll
        for (int q = 0; q < 4; q++) cc[mt][nt][q] = 0.f;

        #pragma unroll
        for (int kt = 0; kt < 8; kt++) {
            #pragma unroll
            for (int nt2 = 0; nt2 < 4; nt2++) {
                const int ntq = chunk * 8 + 2 * nt2 + ntoff;
                uint32_t off = (uint32_t)((ntq * 8 + (lane & 7)) * 136
                                          + kt * 16 + khalf * 8) * 2;
                uint32_t p0, p1, p2, p3;
                ldmx4(p0, p1, p2, p3, sbp + off);
                #pragma unroll
                for (int mt = 0; mt < 2; mt++) {
                    mma16816(cc[mt][2 * nt2 + 0], af[kt][mt], p0, p1);
                    mma16816(cc[mt][2 * nt2 + 1], af[kt][mt], p2, p3);
                }
            }
        }
        #pragma unroll
        for (int ntl = 0; ntl < 8; ntl++) {
            const int col = (chunk * 8 + ntl) * 8 + 2 * tm4;
            float2 bb = make_float2(0.f, 0.f);
            if (half == 2) bb = *(const float2*)(bh1g + col);
            #pragma unroll
            for (int mt = 0; mt < 2; mt++) {
                #pragma unroll
                for (int mh = 0; mh < 2; mh++) {
                    int row = node + td4 + 8 * (2 * mt + mh);
                    float v0 = cc[mt][ntl][2 * mh + 0] + bb.x;
                    float v1 = cc[mt][ntl][2 * mh + 1] + bb.y;
                    if (half == 0)
                        *(float2*)(g_p1 + (size_t)row * 128 + col) = make_float2(v0, v1);
                    else if (half == 1)
                        g_p2h[(size_t)row * 64 + (col >> 1)] = packhf(v0, v1);
                    else
                        *(float2*)(g_p3 + (size_t)row * 128 + col) = make_float2(v0, v1);
                }
            }
        }
    }
}

// ---------------------------------------------------------------------------
// K1: HMMA edge kernel.  384 threads (12 warps), warp = node.
// p2 gathered as packed fp16.
// ---------------------------------------------------------------------------
__global__ __launch_bounds__(384, 1) void k_edge(
    const float* __restrict__ coords,
    const float* __restrict__ edges,
    const float* __restrict__ b1g,
    const float* __restrict__ wx2, const float* __restrict__ bx2,
    const int* __restrict__ ids,
    float* __restrict__ out_coords)
{
    extern __shared__ unsigned char wsm[];
    const uint32_t sb  = s2u(wsm);
    const uint32_t b1A = sb + OFF_B1;
    const uint32_t b2A = sb + OFF_B2;

    __shared__ float dist_sh[384];
    __shared__ float unit_sh[384][3];
    __shared__ int   jid_sh[384];
    __shared__ float px_sh[384];
    __shared__ float b1_sh[128], b2x_sh[128], wx2_sh[128], fr_sh[16];

    const int tid  = threadIdx.x;
    const int w    = tid >> 5;
    const int lane = tid & 31;
    const int td4  = lane >> 2;
    const int tm4  = lane & 3;

    {
        uint4* dst = (uint4*)wsm;
        for (int i = tid; i < WIMG_BYTES / 16; i += 384) dst[i] = g_Bimg[i];
    }
    if (tid < 128) {
        b1_sh[tid]  = b1g[tid];
        b2x_sh[tid] = g_b2x[tid];
        wx2_sh[tid] = wx2[tid];
    }
    if (tid < 16) fr_sh[tid] = expf((float)tid * KFREQ);
    __syncthreads();

    const float fr0 = fr_sh[2 * tm4],     fr1 = fr_sh[2 * tm4 + 1];
    const float fr2 = fr_sh[2 * tm4 + 8], fr3 = fr_sh[2 * tm4 + 9];
    const float bx2v = bx2[0];

    const int qsel  = lane >> 3;
    const int ntoff = qsel >> 1;
    const int khalf = qsel & 1;

    for (int it = 0; it < NITER; it++) {
        const int nodebase = it * NODES_PER_ITER + blockIdx.x * WARPS_PER_CTA;

        {
            int nd = nodebase + (tid >> 5);
            if (nd < BN) {
                int m = tid & 31;
                int jabs = ((nd >> 10) << 10) + ids[nd * 32 + m];
                jid_sh[tid] = jabs;
                float dx = coords[nd * 3 + 0] - coords[jabs * 3 + 0];
                float dy = coords[nd * 3 + 1] - coords[jabs * 3 + 1];
                float dz = coords[nd * 3 + 2] - coords[jabs * 3 + 2];
                float d = sqrtf(dx * dx + dy * dy + dz * dz);
                dist_sh[tid] = d;
                float inv = (d > 0.f) ? (1.f / d) : 0.f;
                unit_sh[tid][0] = dx * inv;
                unit_sh[tid][1] = dy * inv;
                unit_sh[tid][2] = dz * inv;
            }
        }
        __syncthreads();

        const int node = nodebase + w;
        if (node < BN) {
            float dloc[4];
            #pragma unroll
            for (int i = 0; i < 4; i++) dloc[i] = dist_sh[w * 32 + td4 + 8 * i];

            uint32_t ahi[4][2][4];
            #pragma unroll
            for (int kt = 0; kt < 4; kt++) {
                #pragma unroll
                for (int i = 0; i < 4; i++) {
                    float v0, v1, v2, v3;
                    if (kt == 0) {
                        v0 = __sinf(dloc[i] * fr0); v1 = __sinf(dloc[i] * fr1);
                        v2 = __sinf(dloc[i] * fr2); v3 = __sinf(dloc[i] * fr3);
                    } else if (kt == 1) {
                        v0 = __cosf(dloc[i] * fr0); v1 = __cosf(dloc[i] * fr1);
                        v2 = __cosf(dloc[i] * fr2); v3 = __cosf(dloc[i] * fr3);
                    } else {
                        const float* ep = edges
                            + (size_t)(node * 32 + td4 + 8 * i) * 32
                            + (kt - 2) * 16 + 2 * tm4;
                        float2 va = *(const float2*)ep;
                        float2 vb = *(const float2*)(ep + 8);
                        v0 = va.x; v1 = va.y; v2 = vb.x; v3 = vb.y;
                    }
                    int mt = i >> 1, s = i & 1;
                    ahi[kt][mt][s]     = packhf(v0, v1);
                    ahi[kt][mt][2 + s] = packhf(v2, v3);
                }
            }

            uint32_t a2[2][8][4];
            #pragma unroll
            for (int half = 0; half < 2; half++) {
                float c1h[2][8][4];
                #pragma unroll
                for (int mt = 0; mt < 2; mt++)
                #pragma unroll
                for (int nt = 0; nt < 8; nt++)
                #pragma unroll
                for (int q = 0; q < 4; q++) c1h[mt][nt][q] = 0.f;

                #pragma unroll
                for (int kt = 0; kt < 4; kt++) {
                    #pragma unroll
                    for (int nt2 = 0; nt2 < 4; nt2++) {
                        const int ntq = half * 8 + 2 * nt2 + ntoff;
                        uint32_t off = (uint32_t)((ntq * 8 + (lane & 7)) * 72
                                                  + kt * 16 + khalf * 8) * 2;
                        uint32_t p0, p1, p2, p3;
                        ldmx4(p0, p1, p2, p3, b1A + off);
                        #pragma unroll
                        for (int mt = 0; mt < 2; mt++) {
                            mma16816(c1h[mt][2 * nt2 + 0], ahi[kt][mt], p0, p1);
                            mma16816(c1h[mt][2 * nt2 + 1], ahi[kt][mt], p2, p3);
                        }
                    }
                }

                #pragma unroll
                for (int kt2l = 0; kt2l < 4; kt2l++) {
                    #pragma unroll
                    for (int sub = 0; sub < 2; sub++) {
                        const int ntl = 2 * kt2l + sub;
                        const int n0c = (half * 8 + ntl) * 8 + 2 * tm4;
                        float2 pa = *(const float2*)(g_p1 + (size_t)node * 128 + n0c);
                        const float bb0 = b1_sh[n0c], bb1 = b1_sh[n0c + 1];
                        float hs0 = 0.f, hs1 = 0.f;
                        #pragma unroll
                        for (int mt = 0; mt < 2; mt++) {
                            #pragma unroll
                            for (int mh = 0; mh < 2; mh++) {
                                int j = jid_sh[w * 32 + td4 + 8 * (2 * mt + mh)];
                                float2 p2v = unpackhf(g_p2h[(size_t)j * 64 + (n0c >> 1)]);
                                float h0 = fmaxf(c1h[mt][ntl][2 * mh + 0] + pa.x + p2v.x + bb0, 0.f);
                                float h1 = fmaxf(c1h[mt][ntl][2 * mh + 1] + pa.y + p2v.y + bb1, 0.f);
                                hs0 += h0; hs1 += h1;
                                a2[mt][half * 4 + kt2l][mh + 2 * sub] = packhf(h0, h1);
                            }
                        }
                        #pragma unroll
                        for (int o = 4; o < 32; o <<= 1) {
                            hs0 += __shfl_xor_sync(0xffffffffu, hs0, o);
                            hs1 += __shfl_xor_sync(0xffffffffu, hs1, o);
                        }
                        if (td4 == 0) {
                            g_hsum[(size_t)node * 128 + n0c]     = hs0;
                            g_hsum[(size_t)node * 128 + n0c + 1] = hs1;
                        }
                    }
                }
            }

            float px[4] = {0.f, 0.f, 0.f, 0.f};
            #pragma unroll
            for (int half = 0; half < 2; half++) {
                #pragma unroll
                for (int q4 = 0; q4 < 2; q4++) {
                    float c2q[2][4][4];
                    #pragma unroll
                    for (int mt = 0; mt < 2; mt++)
                    #pragma unroll
                    for (int nl = 0; nl < 4; nl++)
                    #pragma unroll
                    for (int q = 0; q < 4; q++) c2q[mt][nl][q] = 0.f;

                    #pragma unroll
                    for (int kt2 = 0; kt2 < 8; kt2++) {
                        #pragma unroll
                        for (int nl2 = 0; nl2 < 2; nl2++) {
                            const int ntq = half * 8 + q4 * 4 + 2 * nl2 + ntoff;
                            uint32_t off = (uint32_t)((ntq * 8 + (lane & 7)) * 136
                                                      + kt2 * 16 + khalf * 8) * 2;
                            uint32_t p0, p1, p2, p3;
                            ldmx4(p0, p1, p2, p3, b2A + off);
                            #pragma unroll
                            for (int mt = 0; mt < 2; mt++) {
                                mma16816(c2q[mt][2 * nl2 + 0], a2[mt][kt2], p0, p1);
                                mma16816(c2q[mt][2 * nl2 + 1], a2[mt][kt2], p2, p3);
                            }
                        }
                    }
                    #pragma unroll
                    for (int nl = 0; nl < 4; nl++) {
                        const int n = half * 64 + q4 * 32 + nl * 8 + 2 * tm4;
                        const float bA = b2x_sh[n], bB = b2x_sh[n + 1];
                        const float wA = wx2_sh[n], wB = wx2_sh[n + 1];
                        #pragma unroll
                        for (int mt = 0; mt < 2; mt++) {
                            px[2 * mt + 0] = fmaf(fmaxf(c2q[mt][nl][0] + bA, 0.f), wA,
                                             fmaf(fmaxf(c2q[mt][nl][1] + bB, 0.f), wB,
                                                  px[2 * mt + 0]));
                            px[2 * mt + 1] = fmaf(fmaxf(c2q[mt][nl][2] + bA, 0.f), wA,
                                             fmaf(fmaxf(c2q[mt][nl][3] + bB, 0.f), wB,
                                                  px[2 * mt + 1]));
                        }
                    }
                }
            }

            #pragma unroll
            for (int i = 0; i < 4; i++) {
                px[i] += __shfl_xor_sync(0xffffffffu, px[i], 1);
                px[i] += __shfl_xor_sync(0xffffffffu, px[i], 2);
                px[i] += bx2v;
            }
            if (tm4 == 0) {
                #pragma unroll
                for (int i = 0; i < 4; i++)
                    px_sh[w * 32 + td4 + 8 * i] = px[i];
            }
            __syncwarp();
            {
                int e = w * 32 + lane;
                float p = px_sh[e];
                float sx = unit_sh[e][0] * p;
                float sy = unit_sh[e][1] * p;
                float sz = unit_sh[e][2] * p;
                #pragma unroll
                for (int o = 16; o > 0; o >>= 1) {
                    sx += __shfl_xor_sync(0xffffffffu, sx, o);
                    sy += __shfl_xor_sync(0xffffffffu, sy, o);
                    sz += __shfl_xor_sync(0xffffffffu, sz, o);
                }
                if (lane == 0) {
                    out_coords[node * 3 + 0] = coords[node * 3 + 0] + sx * (1.f / 32.f);
                    out_coords[node * 3 + 1] = coords[node * 3 + 1] + sy * (1.f / 32.f);
                    out_coords[node * 3 + 2] = coords[node * 3 + 2] + sz * (1.f / 32.f);
                }
            }
        }
        __syncthreads();
    }
}

// ---------------------------------------------------------------------------
// K3: HMMA node update.  Block 128 (4 warps), warp = 16 node-rows, grid 128.
// ---------------------------------------------------------------------------
__global__ __launch_bounds__(128) void k_node(
    const float* __restrict__ emb,
    const float* __restrict__ mask,
    const float* __restrict__ bh2g,
    float* __restrict__ out_emb)
{
    extern __shared__ unsigned char nsm[];
    const uint32_t sbn  = s2u(nsm);
    const uint32_t w2hA = sbn + OFF_W2H;
    const uint32_t wh2A = sbn + OFF_WH2;

    __shared__ float bvec_sh[128], bh2_sh[128];

    const int tid  = threadIdx.x;
    const int w    = tid >> 5;
    const int lane = tid & 31;
    const int td4  = lane >> 2;
    const int tm4  = lane & 3;

    {
        uint4* dst = (uint4*)nsm;
        for (int i = tid; i < NIMG_BYTES / 16; i += 128) dst[i] = g_Nimg[i];
    }
    if (tid < 128) {
        bvec_sh[tid] = g_bvec[tid];
        bh2_sh[tid]  = bh2g[tid];
    }
    __syncthreads();

    const int node0 = blockIdx.x * 64 + w * 16;

    float mskv[2], mscale[2];
    #pragma unroll
    for (int i = 0; i < 2; i++) {
        mskv[i]   = mask[node0 + td4 + 8 * i];
        mscale[i] = mskv[i] * (1.f / 32.f);
    }

    const int qsel  = lane >> 3;
    const int ntoff = qsel >> 1;
    const int khalf = qsel & 1;

    uint32_t a2[8][4];
    #pragma unroll
    for (int half = 0; half < 2; half++) {
        float c1h[8][4];
        #pragma unroll
        for (int nt = 0; nt < 8; nt++)
        #pragma unroll
        for (int q = 0; q < 4; q++) c1h[nt][q] = 0.f;

        #pragma unroll
        for (int kt = 0; kt < 8; kt++) {
            uint32_t af[4];
            #pragma unroll
            for (int i = 0; i < 2; i++) {
                int row = node0 + td4 + 8 * i;
                const float* hp = g_hsum + (size_t)row * 128 + kt * 16 + 2 * tm4;
                float2 va = *(const float2*)hp;
                float2 vb = *(const float2*)(hp + 8);
                float s = mscale[i];
                af[i]     = packhf(va.x * s, va.y * s);
                af[2 + i] = packhf(vb.x * s, vb.y * s);
            }
            #pragma unroll
            for (int nt2 = 0; nt2 < 4; nt2++) {
                const int ntq = half * 8 + 2 * nt2 + ntoff;
                uint32_t off = (uint32_t)((ntq * 8 + (lane & 7)) * 136
                                          + kt * 16 + khalf * 8) * 2;
                uint32_t p0, p1, p2, p3;
                ldmx4(p0, p1, p2, p3, w2hA + off);
                mma16816(c1h[2 * nt2 + 0], af, p0, p1);
                mma16816(c1h[2 * nt2 + 1], af, p2, p3);
            }
        }

        #pragma unroll
        for (int kt2l = 0; kt2l < 4; kt2l++) {
            #pragma unroll
            for (int sub = 0; sub < 2; sub++) {
                const int ntl = 2 * kt2l + sub;
                const int col = (half * 8 + ntl) * 8 + 2 * tm4;
                float2 bv2 = *(const float2*)&bvec_sh[col];
                #pragma unroll
                for (int mh = 0; mh < 2; mh++) {
                    int row = node0 + td4 + 8 * mh;
                    float2 p3v = *(const float2*)(g_p3 + (size_t)row * 128 + col);
                    float h0 = fmaxf(c1h[ntl][2 * mh + 0] + p3v.x + mskv[mh] * bv2.x, 0.f);
                    float h1 = fmaxf(c1h[ntl][2 * mh + 1] + p3v.y + mskv[mh] * bv2.y, 0.f);
                    a2[half * 4 + kt2l][mh + 2 * sub] = packhf(h0, h1);
                }
            }
        }
    }

    #pragma unroll
    for (int half = 0; half < 2; half++) {
        #pragma unroll
        for (int q4 = 0; q4 < 2; q4++) {
            float c2q[4][4];
            #pragma unroll
            for (int nl = 0; nl < 4; nl++)
            #pragma unroll
            for (int q = 0; q < 4; q++) c2q[nl][q] = 0.f;

            #pragma unroll
            for (int kt2 = 0; kt2 < 8; kt2++) {
                #pragma unroll
                for (int nl2 = 0; nl2 < 2; nl2++) {
                    const int ntq = half * 8 + q4 * 4 + 2 * nl2 + ntoff;
                    uint32_t off = (uint32_t)((ntq * 8 + (lane & 7)) * 136
                                              + kt2 * 16 + khalf * 8) * 2;
                    uint32_t p0, p1, p2, p3;
                    ldmx4(p0, p1, p2, p3, wh2A + off);
                    mma16816(c2q[2 * nl2 + 0], a2[kt2], p0, p1);
                    mma16816(c2q[2 * nl2 + 1], a2[kt2], p2, p3);
                }
            }
            #pragma unroll
            for (int nl = 0; nl < 4; nl++) {
                const int col = half * 64 + q4 * 32 + nl * 8 + 2 * tm4;
                float2 b2v = *(const float2*)&bh2_sh[col];
                #pragma unroll
                for (int mh = 0; mh < 2; mh++) {
                    int row = node0 + td4 + 8 * mh;
                    float2 ev = *(const float2*)(emb + (size_t)row * 128 + col);
                    *(float2*)(out_emb + (size_t)row * 128 + col) =
                        make_float2(ev.x + c2q[nl][2 * mh + 0] + b2v.x,
                                    ev.y + c2q[nl][2 * mh + 1] + b2v.y);
                }
            }
        }
    }
}

// ---------------------------------------------------------------------------
extern "C" void kernel_launch(void* const* d_in, const int* in_sizes, int n_in,
                              void* d_out, int out_size)
{
    const float* emb    = (const float*)d_in[0];
    const float* coords = (const float*)d_in[1];
    const float* mask   = (const float*)d_in[2];
    const float* edges  = (const float*)d_in[3];
    const float* we_w1  = (const float*)d_in[4];
    const float* we_b1  = (const float*)d_in[5];
    const float* we_w2  = (const float*)d_in[6];
    const float* we_b2  = (const float*)d_in[7];
    const float* wx_w1  = (const float*)d_in[8];
    const float* wx_b1  = (const float*)d_in[9];
    const float* wx_w2  = (const float*)d_in[10];
    const float* wx_b2  = (const float*)d_in[11];
    const float* wh_w1  = (const float*)d_in[12];
    const float* wh_b1  = (const float*)d_in[13];
    const float* wh_w2  = (const float*)d_in[14];
    const float* wh_b2  = (const float*)d_in[15];
    const int*   ids    = (const int*)d_in[16];

    float* out_emb    = (float*)d_out;
    float* out_coords = (float*)d_out + (size_t)BN * 128;

    static int attr_set = 0;
    if (!attr_set) {
        cudaFuncSetAttribute(k_edge,
                             cudaFuncAttributeMaxDynamicSharedMemorySize,
                             WIMG_BYTES);
        cudaFuncSetAttribute(k_node,
                             cudaFuncAttributeMaxDynamicSharedMemorySize,
                             NIMG_BYTES);
        attr_set = 1;
    }

    k_fold<<<8, 128>>>(we_w2, we_b2, wx_w1, wx_b1, wh_w1, we_w1, wh_w2);

    dim3 pg(64, 3);
    k_proj<<<pg, 128, PIMG_HALF>>>(emb, wh_b1);

    k_edge<<<EDGE_GRID, 384, WIMG_BYTES>>>(coords, edges, we_b1,
                                           wx_w2, wx_b2, ids, out_coords);

    k_node<<<128, 128, NIMG_BYTES>>>(emb, mask, wh_b2, out_emb);
}

// round 17
// speedup vs baseline: 1.2372x; 1.0475x over previous
#include <cuda_runtime.h>
#include <cuda_fp16.h>
#include <math.h>
#include <stdint.h>

// Problem constants
#define Bz 8
#define Nn 1024
#define Mm 32
#define BN (Bz*Nn)            // 8192
#define KFREQ (-0.6140226914650789f)   // -log(10000)/15

#define EDGE_GRID 148
#define WARPS_PER_CTA 12
#define NODES_PER_ITER (EDGE_GRID * WARPS_PER_CTA)   // 1776
#define NITER 5                                       // ceil(8192/1776)

// Edge weight image (bytes): B1 | B2   (plain fp16)
#define OFF_B1 0
#define OFF_B2 18432
#define WIMG_BYTES 53248

// Proj weight image: [W1a^T | W1b^T | Wh1a^T] -> 3 x [128 n][128 k] fp16, stride 272B
#define PIMG_HALF  34816
#define PIMG_BYTES (3 * PIMG_HALF)

// Node weight image: W2h^T | Wh2^T  each [128 n][128 k] fp16, stride 272B
#define OFF_W2H 0
#define OFF_WH2 34816
#define NIMG_BYTES 69632

// ---------------------------------------------------------------------------
// Scratch
// ---------------------------------------------------------------------------
__device__ float    g_p1[BN*128];    // emb @ W1[0:128]
__device__ uint32_t g_p2h[BN*64];    // emb @ W1[128:256], packed half2
__device__ float    g_p3[BN*128];    // emb @ Wh1a + bh1
__device__ float    g_hsum[BN*128];  // sum_j relu-h
__device__ float    g_b2x[128];      // b2 @ Wx1 + bx1
__device__ float    g_bvec[128];     // b2 @ Wh1[128:256]
__device__ uint4 g_Bimg[WIMG_BYTES/16];
__device__ uint4 g_Pimg[PIMG_BYTES/16];
__device__ uint4 g_Nimg[NIMG_BYTES/16];

// ---------------------------------------------------------------------------
// helpers
// ---------------------------------------------------------------------------
__device__ __forceinline__ uint32_t s2u(const void* p) {
    uint32_t a;
    asm("{ .reg .u64 t; cvta.to.shared.u64 t, %1; cvt.u32.u64 %0, t; }"
        : "=r"(a) : "l"(p));
    return a;
}
__device__ __forceinline__ void ldmx4(uint32_t& r0, uint32_t& r1,
                                      uint32_t& r2, uint32_t& r3, uint32_t addr) {
    asm volatile("ldmatrix.sync.aligned.m8n8.x4.shared.b16 {%0,%1,%2,%3}, [%4];"
                 : "=r"(r0), "=r"(r1), "=r"(r2), "=r"(r3) : "r"(addr));
}
__device__ __forceinline__ void mma16816(float* c, const uint32_t* a,
                                         uint32_t b0, uint32_t b1) {
    asm volatile(
        "mma.sync.aligned.m16n8k16.row.col.f32.f16.f16.f32 "
        "{%0,%1,%2,%3}, {%4,%5,%6,%7}, {%8,%9}, {%0,%1,%2,%3};"
        : "+f"(c[0]), "+f"(c[1]), "+f"(c[2]), "+f"(c[3])
        : "r"(a[0]), "r"(a[1]), "r"(a[2]), "r"(a[3]), "r"(b0), "r"(b1));
}
// pack: lower half = f0, upper = f1
__device__ __forceinline__ uint32_t packhf(float f0, float f1) {
    uint32_t r;
    asm("cvt.rn.f16x2.f32 %0, %1, %2;" : "=r"(r) : "f"(f1), "f"(f0));
    return r;
}
__device__ __forceinline__ float2 unpackhf(uint32_t v) {
    __half2 h = *(__half2*)&v;
    return __half22float2(h);
}

// ---------------------------------------------------------------------------
// K-1: fold + all weight-image prep.
// ---------------------------------------------------------------------------
__global__ __launch_bounds__(128) void k_fold(
    const float* __restrict__ w2,  const float* __restrict__ b2,
    const float* __restrict__ wx1, const float* __restrict__ bx1,
    const float* __restrict__ wh1, const float* __restrict__ w1,
    const float* __restrict__ wh2)
{
    __shared__ float w2sh[16][128];
    unsigned char* img  = (unsigned char*)g_Bimg;
    unsigned char* img2 = (unsigned char*)g_Pimg;
    unsigned char* img3 = (unsigned char*)g_Nimg;
    const int c = threadIdx.x;
    const int d0 = blockIdx.x * 16;

    #pragma unroll
    for (int i = 0; i < 16; i++)
        w2sh[i][c] = w2[(d0 + i) * 128 + c];
    __syncthreads();

    float a1[16], a2[16];
    #pragma unroll
    for (int i = 0; i < 16; i++) { a1[i] = 0.f; a2[i] = 0.f; }

    #pragma unroll 2
    for (int k = 0; k < 128; k++) {
        float wA = wx1[k * 128 + c];
        float wB = wh1[(128 + k) * 128 + c];
        #pragma unroll
        for (int i = 0; i < 16; i++) {
            float v = w2sh[i][k];
            a1[i] = fmaf(v, wA, a1[i]);
            a2[i] = fmaf(v, wB, a2[i]);
        }
    }
    #pragma unroll
    for (int i = 0; i < 16; i++) {
        *(__half*)(img + OFF_B2 + (uint32_t)c * 272 + (uint32_t)(d0 + i) * 2)
            = __float2half_rn(a1[i]);
        *(__half*)(img3 + OFF_W2H + (uint32_t)c * 272 + (uint32_t)(d0 + i) * 2)
            = __float2half_rn(a2[i]);
    }

    // B1 image
    #pragma unroll
    for (int j = 0; j < 8; j++) {
        int e = blockIdx.x * 1024 + j * 128 + c;
        int n = e & 127, k = e >> 7;
        *(__half*)(img + OFF_B1 + (uint32_t)n * 144 + (uint32_t)k * 2)
            = __float2half_rn(w1[(256 + k) * 128 + n]);
    }

    // Proj image: n<256: W1ab^T;  n>=256: Wh1a^T
    #pragma unroll
    for (int j = 0; j < 48; j++) {
        int e = blockIdx.x * 6144 + j * 128 + c;
        int k = e / 384;
        int n = e - k * 384;
        float v = (n < 256) ? w1[(k + ((n >> 7) << 7)) * 128 + (n & 127)]
                            : wh1[k * 128 + (n - 256)];
        *(__half*)(img2 + (uint32_t)n * 272 + (uint32_t)k * 2)
            = __float2half_rn(v);
    }

    // Wh2 image
    #pragma unroll
    for (int j = 0; j < 16; j++) {
        int e = blockIdx.x * 2048 + j * 128 + c;
        int n = e & 127, k = e >> 7;
        *(__half*)(img3 + OFF_WH2 + (uint32_t)n * 272 + (uint32_t)k * 2)
            = __float2half_rn(wh2[k * 128 + n]);
    }

    if (blockIdx.x == 0) {
        float s1 = bx1[c], s2 = 0.f;
        for (int k = 0; k < 128; k++) {
            float bk = b2[k];
            s1 = fmaf(bk, wx1[k * 128 + c], s1);
            s2 = fmaf(bk, wh1[(128 + k) * 128 + c], s2);
        }
        g_b2x[c]  = s1;
        g_bvec[c] = s2;
    }
}

// ---------------------------------------------------------------------------
// K0: HMMA projection.  grid (64, 3): x = 128-node group, y = {p1,p2,p3}.
// p2 is stored packed fp16; p3 gets +bh1.
// ---------------------------------------------------------------------------
__global__ __launch_bounds__(128) void k_proj(
    const float* __restrict__ emb, const float* __restrict__ bh1g)
{
    extern __shared__ unsigned char psm[];
    const uint32_t sbp = s2u(psm);

    const int tid  = threadIdx.x;
    const int w    = tid >> 5;
    const int lane = tid & 31;
    const int td4  = lane >> 2;
    const int tm4  = lane & 3;
    const int half = blockIdx.y;

    {
        uint4* dst = (uint4*)psm;
        const uint4* src = g_Pimg + (size_t)half * (PIMG_HALF / 16);
        for (int i = tid; i < PIMG_HALF / 16; i += 128) dst[i] = src[i];
    }
    __syncthreads();

    const int node = blockIdx.x * 128 + w * 32;

    uint32_t af[8][2][4];
    #pragma unroll
    for (int kt = 0; kt < 8; kt++) {
        #pragma unroll
        for (int i = 0; i < 4; i++) {
            int row = node + td4 + 8 * i;
            const float* ep = emb + (size_t)row * 128 + kt * 16 + 2 * tm4;
            float2 va = *(const float2*)ep;
            float2 vb = *(const float2*)(ep + 8);
            int mt = i >> 1, s = i & 1;
            af[kt][mt][s]     = packhf(va.x, va.y);
            af[kt][mt][2 + s] = packhf(vb.x, vb.y);
        }
    }

    const int qsel  = lane >> 3;
    const int ntoff = qsel >> 1;
    const int khalf = qsel & 1;

    #pragma unroll
    for (int chunk = 0; chunk < 2; chunk++) {
        float cc[2][8][4];
        #pragma unroll
        for (int mt = 0; mt < 2; mt++)
        #pragma unroll
        for (int nt = 0; nt < 8; nt++)
        #pragma unroll
        for (int q = 0; q < 4; q++) cc[mt][nt][q] = 0.f;

        #pragma unroll
        for (int kt = 0; kt < 8; kt++) {
            #pragma unroll
            for (int nt2 = 0; nt2 < 4; nt2++) {
                const int ntq = chunk * 8 + 2 * nt2 + ntoff;
                uint32_t off = (uint32_t)((ntq * 8 + (lane & 7)) * 136
                                          + kt * 16 + khalf * 8) * 2;
                uint32_t p0, p1, p2, p3;
                ldmx4(p0, p1, p2, p3, sbp + off);
                #pragma unroll
                for (int mt = 0; mt < 2; mt++) {
                    mma16816(cc[mt][2 * nt2 + 0], af[kt][mt], p0, p1);
                    mma16816(cc[mt][2 * nt2 + 1], af[kt][mt], p2, p3);
                }
            }
        }
        #pragma unroll
        for (int ntl = 0; ntl < 8; ntl++) {
            const int col = (chunk * 8 + ntl) * 8 + 2 * tm4;
            float2 bb = make_float2(0.f, 0.f);
            if (half == 2) bb = *(const float2*)(bh1g + col);
            #pragma unroll
            for (int mt = 0; mt < 2; mt++) {
                #pragma unroll
                for (int mh = 0; mh < 2; mh++) {
                    int row = node + td4 + 8 * (2 * mt + mh);
                    float v0 = cc[mt][ntl][2 * mh + 0] + bb.x;
                    float v1 = cc[mt][ntl][2 * mh + 1] + bb.y;
                    if (half == 0)
                        *(float2*)(g_p1 + (size_t)row * 128 + col) = make_float2(v0, v1);
                    else if (half == 1)
                        g_p2h[(size_t)row * 64 + (col >> 1)] = packhf(v0, v1);
                    else
                        *(float2*)(g_p3 + (size_t)row * 128 + col) = make_float2(v0, v1);
                }
            }
        }
    }
}

// ---------------------------------------------------------------------------
// K1: HMMA edge kernel.  384 threads (12 warps), warp = node.
// All per-iteration shared state is warp-private -> warp-local syncs only,
// so warps self-pipeline instead of convoying on block barriers.
// ---------------------------------------------------------------------------
__global__ __launch_bounds__(384, 1) void k_edge(
    const float* __restrict__ coords,
    const float* __restrict__ edges,
    const float* __restrict__ b1g,
    const float* __restrict__ wx2, const float* __restrict__ bx2,
    const int* __restrict__ ids,
    float* __restrict__ out_coords)
{
    extern __shared__ unsigned char wsm[];
    const uint32_t sb  = s2u(wsm);
    const uint32_t b1A = sb + OFF_B1;
    const uint32_t b2A = sb + OFF_B2;

    __shared__ float dist_sh[384];
    __shared__ float unit_sh[384][3];
    __shared__ int   jid_sh[384];
    __shared__ float px_sh[384];
    __shared__ float b1_sh[128], b2x_sh[128], wx2_sh[128], fr_sh[16];

    const int tid  = threadIdx.x;
    const int w    = tid >> 5;
    const int lane = tid & 31;
    const int td4  = lane >> 2;
    const int tm4  = lane & 3;

    {
        uint4* dst = (uint4*)wsm;
        for (int i = tid; i < WIMG_BYTES / 16; i += 384) dst[i] = g_Bimg[i];
    }
    if (tid < 128) {
        b1_sh[tid]  = b1g[tid];
        b2x_sh[tid] = g_b2x[tid];
        wx2_sh[tid] = wx2[tid];
    }
    if (tid < 16) fr_sh[tid] = expf((float)tid * KFREQ);
    __syncthreads();   // weight image + broadcast tables are block-shared

    const float fr0 = fr_sh[2 * tm4],     fr1 = fr_sh[2 * tm4 + 1];
    const float fr2 = fr_sh[2 * tm4 + 8], fr3 = fr_sh[2 * tm4 + 9];
    const float bx2v = bx2[0];

    const int qsel  = lane >> 3;
    const int ntoff = qsel >> 1;
    const int khalf = qsel & 1;

    for (int it = 0; it < NITER; it++) {
        const int nodebase = it * NODES_PER_ITER + blockIdx.x * WARPS_PER_CTA;
        const int node = nodebase + w;
        if (node >= BN) break;     // tail warps exit immediately (warp-uniform)

        // per-edge setup (warp-private slice of the shared arrays)
        {
            int m = lane;
            int jabs = ((node >> 10) << 10) + ids[node * 32 + m];
            jid_sh[tid] = jabs;
            float dx = coords[node * 3 + 0] - coords[jabs * 3 + 0];
            float dy = coords[node * 3 + 1] - coords[jabs * 3 + 1];
            float dz = coords[node * 3 + 2] - coords[jabs * 3 + 2];
            float d = sqrtf(dx * dx + dy * dy + dz * dz);
            dist_sh[tid] = d;
            float inv = (d > 0.f) ? (1.f / d) : 0.f;
            unit_sh[tid][0] = dx * inv;
            unit_sh[tid][1] = dy * inv;
            unit_sh[tid][2] = dz * inv;
        }
        __syncwarp();

        {
            float dloc[4];
            #pragma unroll
            for (int i = 0; i < 4; i++) dloc[i] = dist_sh[w * 32 + td4 + 8 * i];

            uint32_t ahi[4][2][4];
            #pragma unroll
            for (int kt = 0; kt < 4; kt++) {
                #pragma unroll
                for (int i = 0; i < 4; i++) {
                    float v0, v1, v2, v3;
                    if (kt == 0) {
                        v0 = __sinf(dloc[i] * fr0); v1 = __sinf(dloc[i] * fr1);
                        v2 = __sinf(dloc[i] * fr2); v3 = __sinf(dloc[i] * fr3);
                    } else if (kt == 1) {
                        v0 = __cosf(dloc[i] * fr0); v1 = __cosf(dloc[i] * fr1);
                        v2 = __cosf(dloc[i] * fr2); v3 = __cosf(dloc[i] * fr3);
                    } else {
                        const float* ep = edges
                            + (size_t)(node * 32 + td4 + 8 * i) * 32
                            + (kt - 2) * 16 + 2 * tm4;
                        float2 va = *(const float2*)ep;
                        float2 vb = *(const float2*)(ep + 8);
                        v0 = va.x; v1 = va.y; v2 = vb.x; v3 = vb.y;
                    }
                    int mt = i >> 1, s = i & 1;
                    ahi[kt][mt][s]     = packhf(v0, v1);
                    ahi[kt][mt][2 + s] = packhf(v2, v3);
                }
            }

            uint32_t a2[2][8][4];
            #pragma unroll
            for (int half = 0; half < 2; half++) {
                float c1h[2][8][4];
                #pragma unroll
                for (int mt = 0; mt < 2; mt++)
                #pragma unroll
                for (int nt = 0; nt < 8; nt++)
                #pragma unroll
                for (int q = 0; q < 4; q++) c1h[mt][nt][q] = 0.f;

                #pragma unroll
                for (int kt = 0; kt < 4; kt++) {
                    #pragma unroll
                    for (int nt2 = 0; nt2 < 4; nt2++) {
                        const int ntq = half * 8 + 2 * nt2 + ntoff;
                        uint32_t off = (uint32_t)((ntq * 8 + (lane & 7)) * 72
                                                  + kt * 16 + khalf * 8) * 2;
                        uint32_t p0, p1, p2, p3;
                        ldmx4(p0, p1, p2, p3, b1A + off);
                        #pragma unroll
                        for (int mt = 0; mt < 2; mt++) {
                            mma16816(c1h[mt][2 * nt2 + 0], ahi[kt][mt], p0, p1);
                            mma16816(c1h[mt][2 * nt2 + 1], ahi[kt][mt], p2, p3);
                        }
                    }
                }

                #pragma unroll
                for (int kt2l = 0; kt2l < 4; kt2l++) {
                    #pragma unroll
                    for (int sub = 0; sub < 2; sub++) {
                        const int ntl = 2 * kt2l + sub;
                        const int n0c = (half * 8 + ntl) * 8 + 2 * tm4;
                        float2 pa = *(const float2*)(g_p1 + (size_t)node * 128 + n0c);
                        const float bb0 = b1_sh[n0c], bb1 = b1_sh[n0c + 1];
                        float hs0 = 0.f, hs1 = 0.f;
                        #pragma unroll
                        for (int mt = 0; mt < 2; mt++) {
                            #pragma unroll
                            for (int mh = 0; mh < 2; mh++) {
                                int j = jid_sh[w * 32 + td4 + 8 * (2 * mt + mh)];
                                float2 p2v = unpackhf(g_p2h[(size_t)j * 64 + (n0c >> 1)]);
                                float h0 = fmaxf(c1h[mt][ntl][2 * mh + 0] + pa.x + p2v.x + bb0, 0.f);
                                float h1 = fmaxf(c1h[mt][ntl][2 * mh + 1] + pa.y + p2v.y + bb1, 0.f);
                                hs0 += h0; hs1 += h1;
                                a2[mt][half * 4 + kt2l][mh + 2 * sub] = packhf(h0, h1);
                            }
                        }
                        #pragma unroll
                        for (int o = 4; o < 32; o <<= 1) {
                            hs0 += __shfl_xor_sync(0xffffffffu, hs0, o);
                            hs1 += __shfl_xor_sync(0xffffffffu, hs1, o);
                        }
                        if (td4 == 0) {
                            g_hsum[(size_t)node * 128 + n0c]     = hs0;
                            g_hsum[(size_t)node * 128 + n0c + 1] = hs1;
                        }
                    }
                }
            }

            float px[4] = {0.f, 0.f, 0.f, 0.f};
            #pragma unroll
            for (int half = 0; half < 2; half++) {
                #pragma unroll
                for (int q4 = 0; q4 < 2; q4++) {
                    float c2q[2][4][4];
                    #pragma unroll
                    for (int mt = 0; mt < 2; mt++)
                    #pragma unroll
                    for (int nl = 0; nl < 4; nl++)
                    #pragma unroll
                    for (int q = 0; q < 4; q++) c2q[mt][nl][q] = 0.f;

                    #pragma unroll
                    for (int kt2 = 0; kt2 < 8; kt2++) {
                        #pragma unroll
                        for (int nl2 = 0; nl2 < 2; nl2++) {
                            const int ntq = half * 8 + q4 * 4 + 2 * nl2 + ntoff;
                            uint32_t off = (uint32_t)((ntq * 8 + (lane & 7)) * 136
                                                      + kt2 * 16 + khalf * 8) * 2;
                            uint32_t p0, p1, p2, p3;
                            ldmx4(p0, p1, p2, p3, b2A + off);
                            #pragma unroll
                            for (int mt = 0; mt < 2; mt++) {
                                mma16816(c2q[mt][2 * nl2 + 0], a2[mt][kt2], p0, p1);
                                mma16816(c2q[mt][2 * nl2 + 1], a2[mt][kt2], p2, p3);
                            }
                        }
                    }
                    #pragma unroll
                    for (int nl = 0; nl < 4; nl++) {
                        const int n = half * 64 + q4 * 32 + nl * 8 + 2 * tm4;
                        const float bA = b2x_sh[n], bB = b2x_sh[n + 1];
                        const float wA = wx2_sh[n], wB = wx2_sh[n + 1];
                        #pragma unroll
                        for (int mt = 0; mt < 2; mt++) {
                            px[2 * mt + 0] = fmaf(fmaxf(c2q[mt][nl][0] + bA, 0.f), wA,
                                             fmaf(fmaxf(c2q[mt][nl][1] + bB, 0.f), wB,
                                                  px[2 * mt + 0]));
                            px[2 * mt + 1] = fmaf(fmaxf(c2q[mt][nl][2] + bA, 0.f), wA,
                                             fmaf(fmaxf(c2q[mt][nl][3] + bB, 0.f), wB,
                                                  px[2 * mt + 1]));
                        }
                    }
                }
            }

            #pragma unroll
            for (int i = 0; i < 4; i++) {
                px[i] += __shfl_xor_sync(0xffffffffu, px[i], 1);
                px[i] += __shfl_xor_sync(0xffffffffu, px[i], 2);
                px[i] += bx2v;
            }
            if (tm4 == 0) {
                #pragma unroll
                for (int i = 0; i < 4; i++)
                    px_sh[w * 32 + td4 + 8 * i] = px[i];
            }
            __syncwarp();
            {
                int e = w * 32 + lane;
                float p = px_sh[e];
                float sx = unit_sh[e][0] * p;
                float sy = unit_sh[e][1] * p;
                float sz = unit_sh[e][2] * p;
                #pragma unroll
                for (int o = 16; o > 0; o >>= 1) {
                    sx += __shfl_xor_sync(0xffffffffu, sx, o);
                    sy += __shfl_xor_sync(0xffffffffu, sy, o);
                    sz += __shfl_xor_sync(0xffffffffu, sz, o);
                }
                if (lane == 0) {
                    out_coords[node * 3 + 0] = coords[node * 3 + 0] + sx * (1.f / 32.f);
                    out_coords[node * 3 + 1] = coords[node * 3 + 1] + sy * (1.f / 32.f);
                    out_coords[node * 3 + 2] = coords[node * 3 + 2] + sz * (1.f / 32.f);
                }
            }
        }
        __syncwarp();   // warp-local: next iteration overwrites this warp's slices
    }
}

// ---------------------------------------------------------------------------
// K3: HMMA node update.  Block 128 (4 warps), warp = 16 node-rows, grid 128.
// ---------------------------------------------------------------------------
__global__ __launch_bounds__(128) void k_node(
    const float* __restrict__ emb,
    const float* __restrict__ mask,
    const float* __restrict__ bh2g,
    float* __restrict__ out_emb)
{
    extern __shared__ unsigned char nsm[];
    const uint32_t sbn  = s2u(nsm);
    const uint32_t w2hA = sbn + OFF_W2H;
    const uint32_t wh2A = sbn + OFF_WH2;

    __shared__ float bvec_sh[128], bh2_sh[128];

    const int tid  = threadIdx.x;
    const int w    = tid >> 5;
    const int lane = tid & 31;
    const int td4  = lane >> 2;
    const int tm4  = lane & 3;

    {
        uint4* dst = (uint4*)nsm;
        for (int i = tid; i < NIMG_BYTES / 16; i += 128) dst[i] = g_Nimg[i];
    }
    if (tid < 128) {
        bvec_sh[tid] = g_bvec[tid];
        bh2_sh[tid]  = bh2g[tid];
    }
    __syncthreads();

    const int node0 = blockIdx.x * 64 + w * 16;

    float mskv[2], mscale[2];
    #pragma unroll
    for (int i = 0; i < 2; i++) {
        mskv[i]   = mask[node0 + td4 + 8 * i];
        mscale[i] = mskv[i] * (1.f / 32.f);
    }

    const int qsel  = lane >> 3;
    const int ntoff = qsel >> 1;
    const int khalf = qsel & 1;

    uint32_t a2[8][4];
    #pragma unroll
    for (int half = 0; half < 2; half++) {
        float c1h[8][4];
        #pragma unroll
        for (int nt = 0; nt < 8; nt++)
        #pragma unroll
        for (int q = 0; q < 4; q++) c1h[nt][q] = 0.f;

        #pragma unroll
        for (int kt = 0; kt < 8; kt++) {
            uint32_t af[4];
            #pragma unroll
            for (int i = 0; i < 2; i++) {
                int row = node0 + td4 + 8 * i;
                const float* hp = g_hsum + (size_t)row * 128 + kt * 16 + 2 * tm4;
                float2 va = *(const float2*)hp;
                float2 vb = *(const float2*)(hp + 8);
                float s = mscale[i];
                af[i]     = packhf(va.x * s, va.y * s);
                af[2 + i] = packhf(vb.x * s, vb.y * s);
            }
            #pragma unroll
            for (int nt2 = 0; nt2 < 4; nt2++) {
                const int ntq = half * 8 + 2 * nt2 + ntoff;
                uint32_t off = (uint32_t)((ntq * 8 + (lane & 7)) * 136
                                          + kt * 16 + khalf * 8) * 2;
                uint32_t p0, p1, p2, p3;
                ldmx4(p0, p1, p2, p3, w2hA + off);
                mma16816(c1h[2 * nt2 + 0], af, p0, p1);
                mma16816(c1h[2 * nt2 + 1], af, p2, p3);
            }
        }

        #pragma unroll
        for (int kt2l = 0; kt2l < 4; kt2l++) {
            #pragma unroll
            for (int sub = 0; sub < 2; sub++) {
                const int ntl = 2 * kt2l + sub;
                const int col = (half * 8 + ntl) * 8 + 2 * tm4;
                float2 bv2 = *(const float2*)&bvec_sh[col];
                #pragma unroll
                for (int mh = 0; mh < 2; mh++) {
                    int row = node0 + td4 + 8 * mh;
                    float2 p3v = *(const float2*)(g_p3 + (size_t)row * 128 + col);
                    float h0 = fmaxf(c1h[ntl][2 * mh + 0] + p3v.x + mskv[mh] * bv2.x, 0.f);
                    float h1 = fmaxf(c1h[ntl][2 * mh + 1] + p3v.y + mskv[mh] * bv2.y, 0.f);
                    a2[half * 4 + kt2l][mh + 2 * sub] = packhf(h0, h1);
                }
            }
        }
    }

    #pragma unroll
    for (int half = 0; half < 2; half++) {
        #pragma unroll
        for (int q4 = 0; q4 < 2; q4++) {
            float c2q[4][4];
            #pragma unroll
            for (int nl = 0; nl < 4; nl++)
            #pragma unroll
            for (int q = 0; q < 4; q++) c2q[nl][q] = 0.f;

            #pragma unroll
            for (int kt2 = 0; kt2 < 8; kt2++) {
                #pragma unroll
                for (int nl2 = 0; nl2 < 2; nl2++) {
                    const int ntq = half * 8 + q4 * 4 + 2 * nl2 + ntoff;
                    uint32_t off = (uint32_t)((ntq * 8 + (lane & 7)) * 136
                                              + kt2 * 16 + khalf * 8) * 2;
                    uint32_t p0, p1, p2, p3;
                    ldmx4(p0, p1, p2, p3, wh2A + off);
                    mma16816(c2q[2 * nl2 + 0], a2[kt2], p0, p1);
                    mma16816(c2q[2 * nl2 + 1], a2[kt2], p2, p3);
                }
            }
            #pragma unroll
            for (int nl = 0; nl < 4; nl++) {
                const int col = half * 64 + q4 * 32 + nl * 8 + 2 * tm4;
                float2 b2v = *(const float2*)&bh2_sh[col];
                #pragma unroll
                for (int mh = 0; mh < 2; mh++) {
                    int row = node0 + td4 + 8 * mh;
                    float2 ev = *(const float2*)(emb + (size_t)row * 128 + col);
                    *(float2*)(out_emb + (size_t)row * 128 + col) =
                        make_float2(ev.x + c2q[nl][2 * mh + 0] + b2v.x,
                                    ev.y + c2q[nl][2 * mh + 1] + b2v.y);
                }
            }
        }
    }
}

// ---------------------------------------------------------------------------
extern "C" void kernel_launch(void* const* d_in, const int* in_sizes, int n_in,
                              void* d_out, int out_size)
{
    const float* emb    = (const float*)d_in[0];
    const float* coords = (const float*)d_in[1];
    const float* mask   = (const float*)d_in[2];
    const float* edges  = (const float*)d_in[3];
    const float* we_w1  = (const float*)d_in[4];
    const float* we_b1  = (const float*)d_in[5];
    const float* we_w2  = (const float*)d_in[6];
    const float* we_b2  = (const float*)d_in[7];
    const float* wx_w1  = (const float*)d_in[8];
    const float* wx_b1  = (const float*)d_in[9];
    const float* wx_w2  = (const float*)d_in[10];
    const float* wx_b2  = (const float*)d_in[11];
    const float* wh_w1  = (const float*)d_in[12];
    const float* wh_b1  = (const float*)d_in[13];
    const float* wh_w2  = (const float*)d_in[14];
    const float* wh_b2  = (const float*)d_in[15];
    const int*   ids    = (const int*)d_in[16];

    float* out_emb    = (float*)d_out;
    float* out_coords = (float*)d_out + (size_t)BN * 128;

    static int attr_set = 0;
    if (!attr_set) {
        cudaFuncSetAttribute(k_edge,
                             cudaFuncAttributeMaxDynamicSharedMemorySize,
                             WIMG_BYTES);
        cudaFuncSetAttribute(k_node,
                             cudaFuncAttributeMaxDynamicSharedMemorySize,
                             NIMG_BYTES);
        attr_set = 1;
    }

    k_fold<<<8, 128>>>(we_w2, we_b2, wx_w1, wx_b1, wh_w1, we_w1, wh_w2);

    dim3 pg(64, 3);
    k_proj<<<pg, 128, PIMG_HALF>>>(emb, wh_b1);

    k_edge<<<EDGE_GRID, 384, WIMG_BYTES>>>(coords, edges, we_b1,
                                           wx_w2, wx_b2, ids, out_coords);

    k_node<<<128, 128, NIMG_BYTES>>>(emb, mask, wh_b2, out_emb);
}